// round 5
// baseline (speedup 1.0000x reference)
#include <cuda_runtime.h>
#include <math.h>

#define NN 63
#define NP (NN*NN)          // 3969
#define NP64 4032
#define BATCH 256
#define KS 7
#define ML 3

typedef unsigned long long u64t;

__device__ __forceinline__ u64t pk2(float lo, float hi) {
    u64t r; asm("mov.b64 %0,{%1,%2};" : "=l"(r) : "f"(lo), "f"(hi)); return r;
}
__device__ __forceinline__ float2 upk2(u64t v) {
    float2 f; asm("mov.b64 {%0,%1},%2;" : "=f"(f.x), "=f"(f.y) : "l"(v)); return f;
}
__device__ __forceinline__ u64t ffma2(u64t a, u64t b, u64t c) {
    u64t d; asm("fma.rn.f32x2 %0,%1,%2,%3;" : "=l"(d) : "l"(a), "l"(b), "l"(c)); return d;
}
__device__ __forceinline__ float hadd2(u64t v) { float2 f = upk2(v); return f.x + f.y; }

// ---------------- device scratch ----------------
__device__ float g_cosT[33*64];     // rows 0..32, col63=0
__device__ float g_sinT[33*64];
__device__ float g_ttcD[63*64];     // [n][2*k2+d] duplicated cos
__device__ float g_ttsD[63*64];     // [n][2*k2+d] duplicated NEGATED sin
__device__ float g_w1[BATCH*147];
__device__ float g_w2[BATCH*147];
__device__ float g_a1[BATCH*25*32];
__device__ float g_a2[BATCH*81*32];
__device__ float g_a3[BATCH*289*32];
__device__ float g_a4[BATCH*1089*32];
__device__ float g_h [BATCH*2*NP];
__device__ float g_blocksum[BATCH];

__device__ __forceinline__ float gelu_exact(float v) {
    return v * 0.5f * (1.0f + erff(v * 0.70710678118654752f));
}

__global__ void init_tw_kernel() {
    int idx = blockIdx.x * blockDim.x + threadIdx.x;
    if (idx < 33*64) {
        int k = idx >> 6, n = idx & 63;
        if (n < 63) {
            float ang = 6.28318530717958647692f * (float)((k * n) % NN) / 63.0f;
            g_cosT[idx] = cosf(ang);
            g_sinT[idx] = sinf(ang);
        } else { g_cosT[idx] = 0.f; g_sinT[idx] = 0.f; }
    }
    if (idx < 63*64) {
        int n = idx >> 6, t = idx & 63, k2 = t >> 1;
        float ang = 6.28318530717958647692f * (float)((k2 * n) % NN) / 63.0f;
        g_ttcD[idx] = cosf(ang);
        g_ttsD[idx] = -sinf(ang);
    }
}

// ---------------- hypernet ----------------
__global__ void hyper_kernel(const float* __restrict__ kA,
                             const float* __restrict__ w1a, const float* __restrict__ b1a,
                             const float* __restrict__ w2a, const float* __restrict__ b2a,
                             const float* __restrict__ w1b, const float* __restrict__ b1b,
                             const float* __restrict__ w2b, const float* __restrict__ b2b) {
    int b = blockIdx.x;
    __shared__ float a[9], h1[100], h2[100];
    int t = threadIdx.x;
    if (t < 9) a[t] = kA[b*9 + t];
    __syncthreads();
    if (t < 100) {
        float s = b1a[t];
        #pragma unroll
        for (int i = 0; i < 9; i++) s += a[i] * w1a[i*100 + t];
        h1[t] = gelu_exact(s);
    } else if (t < 200) {
        int h = t - 100;
        float s = b1b[h];
        #pragma unroll
        for (int i = 0; i < 9; i++) s += a[i] * w1b[i*100 + h];
        h2[h] = gelu_exact(s);
    }
    __syncthreads();
    for (int o = t; o < 147; o += blockDim.x) {
        float s1 = b2a[o], s2 = b2b[o];
        for (int h = 0; h < 100; h++) {
            s1 += h1[h] * w2a[h*147 + o];
            s2 += h2[h] * w2b[h*147 + o];
        }
        g_w1[b*147 + o] = s1;
        g_w2[b*147 + o] = s2;
    }
}

// ---------------- ConvTranspose chain ----------------
__global__ void ct1_kernel(const float* __restrict__ kA,
                           const float* __restrict__ w, const float* __restrict__ bias) {
    int b = blockIdx.x;
    __shared__ float a[9];
    if (threadIdx.x < 9) a[threadIdx.x] = kA[b*9 + threadIdx.x];
    __syncthreads();
    for (int el = threadIdx.x; el < 32*25; el += blockDim.x) {
        int pix = el >> 5, o = el & 31;
        int y = pix / 5, x = pix % 5;
        float acc = bias[o];
        int kys[2], iys[2], nky, kxs[2], ixs[2], nkx;
        if (y & 1) { nky = 2; kys[0]=0; iys[0]=(y+1)>>1; kys[1]=2; iys[1]=(y-1)>>1; }
        else       { nky = 1; kys[0]=1; iys[0]=y>>1; }
        if (x & 1) { nkx = 2; kxs[0]=0; ixs[0]=(x+1)>>1; kxs[1]=2; ixs[1]=(x-1)>>1; }
        else       { nkx = 1; kxs[0]=1; ixs[0]=x>>1; }
        for (int p = 0; p < nky; p++)
            for (int q = 0; q < nkx; q++)
                acc += a[iys[p]*3 + ixs[q]] * w[o*9 + kys[p]*3 + kxs[q]];
        g_a1[(b*25 + pix)*32 + o] = gelu_exact(acc);
    }
}

template <int IN_H>
__global__ void __launch_bounds__(256) ct_mid_kernel(const float* __restrict__ in,
                              const float* __restrict__ w,
                              const float* __restrict__ bias, float* __restrict__ out) {
    constexpr int OUT_H = 2*IN_H - 1;
    constexpr int IN_SZ = IN_H*IN_H;
    constexpr int OUT_SZ = OUT_H*OUT_H;
    __shared__ float s_in[IN_SZ*32];
    __shared__ float s_w[9*8*32];
    __shared__ float s_b[8];
    int b = blockIdx.x, og = blockIdx.y, tid = threadIdx.x;
    int o_base = og * 8;
    const float4* gin = (const float4*)(in + (size_t)b * IN_SZ * 32);
    float4* s_in4w = (float4*)s_in;
    for (int idx = tid; idx < IN_SZ*8; idx += 256) s_in4w[idx] = gin[idx];
    for (int idx = tid; idx < 2304; idx += 256) {
        int k = idx >> 8, r = idx & 255, ol = r >> 5, i = r & 31;
        s_w[idx] = w[(i*32 + o_base + ol)*9 + k];
    }
    if (tid < 8) s_b[tid] = bias[o_base + tid];
    __syncthreads();

    const float4* s_in4 = (const float4*)s_in;
    const float4* s_w4  = (const float4*)s_w;
    for (int pix = tid; pix < OUT_SZ; pix += 256) {
        int y = pix / OUT_H, x = pix % OUT_H;
        float acc[8];
        #pragma unroll
        for (int ol = 0; ol < 8; ol++) acc[ol] = s_b[ol];
        int kys[2], iys[2], nky, kxs[2], ixs[2], nkx;
        if (y & 1) { nky = 2; kys[0]=0; iys[0]=(y+1)>>1; kys[1]=2; iys[1]=(y-1)>>1; }
        else       { nky = 1; kys[0]=1; iys[0]=y>>1; }
        if (x & 1) { nkx = 2; kxs[0]=0; ixs[0]=(x+1)>>1; kxs[1]=2; ixs[1]=(x-1)>>1; }
        else       { nkx = 1; kxs[0]=1; ixs[0]=x>>1; }
        for (int p = 0; p < nky; p++)
            for (int q = 0; q < nkx; q++) {
                int base4 = (iys[p]*IN_H + ixs[q]) * 8;
                int kk = kys[p]*3 + kxs[q];
                #pragma unroll
                for (int c4 = 0; c4 < 8; c4++) {
                    float4 v = s_in4[base4 + c4];
                    #pragma unroll
                    for (int ol = 0; ol < 8; ol++) {
                        float4 wv = s_w4[kk*64 + ol*8 + c4];
                        acc[ol] += v.x*wv.x + v.y*wv.y + v.z*wv.z + v.w*wv.w;
                    }
                }
            }
        float* ob = out + ((size_t)(b*OUT_SZ + pix))*32 + o_base;
        float4 o0 = {gelu_exact(acc[0]), gelu_exact(acc[1]), gelu_exact(acc[2]), gelu_exact(acc[3])};
        float4 o1 = {gelu_exact(acc[4]), gelu_exact(acc[5]), gelu_exact(acc[6]), gelu_exact(acc[7])};
        *(float4*)(ob)     = o0;
        *(float4*)(ob + 4) = o1;
    }
}

__global__ void __launch_bounds__(256) ct5_kernel(const float* __restrict__ w, const float* __restrict__ bias) {
    __shared__ float s_w[9*2*32];
    int b = blockIdx.x, tid = threadIdx.x;
    for (int idx = tid; idx < 576; idx += 256) {
        int k = idx / 64, r = idx & 63, o = r >> 5, i = r & 31;
        s_w[idx] = w[i*18 + o*9 + k];
    }
    __syncthreads();
    float b0 = bias[0], b1 = bias[1];
    const float4* s_w4 = (const float4*)s_w;
    const float4* gin = (const float4*)(g_a4 + (size_t)b * 1089 * 32);
    for (int pix = tid; pix < NP; pix += 256) {
        int y = pix / NN, x = pix % NN;
        float acc0 = b0, acc1 = b1;
        int kys[2], iys[2], nky, kxs[2], ixs[2], nkx;
        if (y & 1) { nky = 1; kys[0]=1; iys[0]=(y+1)>>1; }
        else       { nky = 2; kys[0]=0; iys[0]=(y+2)>>1; kys[1]=2; iys[1]=y>>1; }
        if (x & 1) { nkx = 1; kxs[0]=1; ixs[0]=(x+1)>>1; }
        else       { nkx = 2; kxs[0]=0; ixs[0]=(x+2)>>1; kxs[1]=2; ixs[1]=x>>1; }
        for (int p = 0; p < nky; p++)
            for (int q = 0; q < nkx; q++) {
                int base4 = (iys[p]*33 + ixs[q]) * 8;
                int kk = kys[p]*3 + kxs[q];
                #pragma unroll
                for (int c4 = 0; c4 < 8; c4++) {
                    float4 v = __ldg(gin + base4 + c4);
                    float4 w0 = s_w4[kk*16 + c4];
                    float4 w1 = s_w4[kk*16 + 8 + c4];
                    acc0 += v.x*w0.x + v.y*w0.y + v.z*w0.z + v.w*w0.w;
                    acc1 += v.x*w1.x + v.y*w1.y + v.z*w1.z + v.w*w1.w;
                }
            }
        g_h[((size_t)b*2 + 0)*NP + pix] = acc0;
        g_h[((size_t)b*2 + 1)*NP + pix] = acc1;
    }
}

// ---------------- persistent per-sample solver ----------------
#define OFF_SXP 0                        // 65x68 = 4420
#define OFF_SRP 4420                     // 69x72 = 4968
#define OFF_T   (OFF_SRP + 4968)         // 3*4968 = 14904
#define OFF_PR  (OFF_T + 14904)          // [k2<32][64] = 2048
#define OFF_PI  (OFF_PR + 2048)
#define OFF_CR  (OFF_PI + 2048)          // [k2<32][68] = 2176 (transposed, 16B rows)
#define OFF_CI  (OFF_CR + 2176)
#define OFF_DR  (OFF_CI + 2176)          // [m][32] = 2016
#define OFF_DI  (OFF_DR + 2016)
#define OFF_WCR (OFF_DI + 2016)          // [k1*32+k2] 2016
#define OFF_WCI (OFF_WCR + 2016)
#define OFF_MC  (OFF_WCI + 2016)         // [33][64] 2112
#define OFF_MS  (OFF_MC + 2112)
#define OFF_TTC (OFF_MS + 2112)          // [n][2*k2] duplicated 4032
#define OFF_TTS (OFF_TTC + 4032)         // duplicated negated sin 4032
#define OFF_W1  (OFF_TTS + 4032)
#define OFF_W2  (OFF_W1 + 160)
#define OFF_KA  (OFF_W2 + 160)
#define SMEM_FLOATS (OFF_KA + 16)        // 53428 floats = 213712 B

__global__ void __launch_bounds__(512) solver_kernel(const float* __restrict__ x_in,
                              const float* __restrict__ f_in,
                              const float* __restrict__ kA) {
    extern __shared__ float sm[];
    float* sxp  = sm + OFF_SXP;
    float* srp  = sm + OFF_SRP;
    float* sT   = sm + OFF_T;
    float* sPr  = sm + OFF_PR;
    float* sPi  = sm + OFF_PI;
    float* sCr  = sm + OFF_CR;
    float* sCi  = sm + OFF_CI;
    float* sDr  = sm + OFF_DR;
    float* sDi  = sm + OFF_DI;
    float* swcr = sm + OFF_WCR;
    float* swci = sm + OFF_WCI;
    float* smc  = sm + OFF_MC;
    float* sms  = sm + OFF_MS;
    float* sw1  = sm + OFF_W1;
    float* sw2  = sm + OFF_W2;
    float* ska  = sm + OFF_KA;

    int b = blockIdx.x, tid = threadIdx.x;
    const int T = 512;
    const float inv = 0.12598815766974242f;  // 1/sqrt(63)

    // ---- init ----
    float fr[8];
    #pragma unroll
    for (int p = 0; p < 8; p++) {
        int el = tid + p*T;
        fr[p] = 0.f;
        if (el < NP64) {
            int i = el >> 6, j = el & 63;
            if (j < 63) {
                fr[p] = f_in[b*NP + i*NN + j];
                sxp[(i+1)*68 + (j+1)] = x_in[b*NP + i*NN + j];
            }
        }
    }
    for (int el = tid; el < 33*64; el += T) { smc[el] = g_cosT[el]; sms[el] = g_sinT[el]; }
    for (int el = tid; el < 63*64; el += T) { sm[OFF_TTC + el] = g_ttcD[el]; sm[OFF_TTS + el] = g_ttsD[el]; }
    for (int c = tid; c < 65; c += T) {
        sxp[c] = (c == 64) ? 1.f : 0.f;
        sxp[64*68 + c] = 1.f;
    }
    for (int r = tid; r < 65; r += T) {
        sxp[r*68] = (r == 64) ? 1.f : 0.f;
        sxp[r*68 + 64] = 1.f;
    }
    for (int el = tid; el < 4968; el += T) srp[el] = 0.f;
    for (int el = tid; el < 14904; el += T) sT[el] = 0.f;
    for (int el = tid; el < 2048*2 + 2176*2; el += T) sPr[el] = 0.f;  // P and C regions
    for (int el = tid; el < 2016; el += T) {
        int k1 = el >> 5, k2 = el & 31;
        int pix = k1*NN + k2;
        swcr[el] = g_h[(size_t)b*2*NP + 2*pix];
        swci[el] = g_h[(size_t)b*2*NP + 2*pix + 1];
    }
    if (tid < 9) ska[tid] = kA[b*9 + tid];
    for (int el = tid; el < 147; el += T) {
        sw1[el] = g_w1[b*147 + el];
        sw2[el] = g_w2[b*147 + el];
    }
    __syncthreads();

    for (int iter = 0; iter < 5; iter++) {
        // ---- (a) residual -> srp ----
        #pragma unroll
        for (int p = 0; p < 8; p++) {
            int el = tid + p*T;
            if (el >= NP64) break;
            int i = el >> 6, j = el & 63;
            if (j >= 63) continue;
            const float* xb = sxp + i*68 + j;
            float acc = ska[0]*xb[0] + ska[1]*xb[1] + ska[2]*xb[2]
                      + ska[3]*xb[68] + ska[4]*xb[69] + ska[5]*xb[70]
                      + ska[6]*xb[136] + ska[7]*xb[137] + ska[8]*xb[138];
            srp[(i+3)*72 + j + 4] = fr[p] - acc;
        }
        __syncthreads();

        // ---- (b) stage1: t[c] = conv7(r, w1[c]) — channel-blocked ----
        for (int w = tid; w < 1024; w += T) {
            int i = w >> 4, g = w & 15;
            if (i >= 63) continue;
            int j0 = g << 2;
            float4 A0 = {0,0,0,0}, A1 = {0,0,0,0}, A2 = {0,0,0,0};
            #pragma unroll
            for (int u = 0; u < 7; u++) {
                const float4* rp = (const float4*)(srp + (i+u)*72 + j0);
                float4 Ra = rp[0], Rb = rp[1], Rc = rp[2];
                float rr[12] = {Ra.x,Ra.y,Ra.z,Ra.w, Rb.x,Rb.y,Rb.z,Rb.w, Rc.x,Rc.y,Rc.z,Rc.w};
                #pragma unroll
                for (int v = 0; v < 7; v++) {
                    float w0 = sw1[u*7 + v];
                    float w1 = sw1[49 + u*7 + v];
                    float w2 = sw1[98 + u*7 + v];
                    A0.x += rr[v+1]*w0; A0.y += rr[v+2]*w0; A0.z += rr[v+3]*w0; A0.w += rr[v+4]*w0;
                    A1.x += rr[v+1]*w1; A1.y += rr[v+2]*w1; A1.z += rr[v+3]*w1; A1.w += rr[v+4]*w1;
                    A2.x += rr[v+1]*w2; A2.y += rr[v+2]*w2; A2.z += rr[v+3]*w2; A2.w += rr[v+4]*w2;
                }
            }
            float* o0 = sT + (i+3)*72 + j0 + 4;
            float* o1 = o0 + 4968;
            float* o2 = o1 + 4968;
            if (g < 15) {
                *(float4*)o0 = A0; *(float4*)o1 = A1; *(float4*)o2 = A2;
            } else {
                o0[0]=A0.x; o0[1]=A0.y; o0[2]=A0.z;
                o1[0]=A1.x; o1[1]=A1.y; o1[2]=A1.z;
                o2[0]=A2.x; o2[1]=A2.y; o2[2]=A2.z;
            }
        }
        __syncthreads();

        // ---- (c) stage2: x += sum_c conv7(t[c], w2[c]) ----
        for (int w = tid; w < 1024; w += T) {
            int i = w >> 4, g = w & 15;
            if (i >= 63) continue;
            int j0 = g << 2;
            float a0=0.f, a1=0.f, a2=0.f, a3=0.f;
            #pragma unroll
            for (int c = 0; c < 3; c++) {
                const float* tb = sT + c*4968;
                const float* wc_ = sw2 + c*49;
                #pragma unroll
                for (int u = 0; u < 7; u++) {
                    const float4* rp = (const float4*)(tb + (i+u)*72 + j0);
                    float4 Ra = rp[0], Rb = rp[1], Rc = rp[2];
                    float rr[12] = {Ra.x,Ra.y,Ra.z,Ra.w, Rb.x,Rb.y,Rb.z,Rb.w, Rc.x,Rc.y,Rc.z,Rc.w};
                    #pragma unroll
                    for (int v = 0; v < 7; v++) {
                        float wv = wc_[u*7 + v];
                        a0 += rr[v+1]*wv; a1 += rr[v+2]*wv;
                        a2 += rr[v+3]*wv; a3 += rr[v+4]*wv;
                    }
                }
            }
            float* xo = sxp + (i+1)*68 + j0 + 1;
            xo[0] += a0; xo[1] += a1; xo[2] += a2;
            if (g < 15) xo[3] += a3;
        }
        __syncthreads();

        // ---- (d) residual -> srp ----
        #pragma unroll
        for (int p = 0; p < 8; p++) {
            int el = tid + p*T;
            if (el >= NP64) break;
            int i = el >> 6, j = el & 63;
            if (j >= 63) continue;
            const float* xb = sxp + i*68 + j;
            float acc = ska[0]*xb[0] + ska[1]*xb[1] + ska[2]*xb[2]
                      + ska[3]*xb[68] + ska[4]*xb[69] + ska[5]*xb[70]
                      + ska[6]*xb[136] + ska[7]*xb[137] + ska[8]*xb[138];
            srp[(i+3)*72 + j + 4] = fr[p] - acc;
        }
        __syncthreads();

        // ---- (P) P[k2][m] = inv * sum_n r[m,n] conj(W[k2,n]); packed over (m0,m1) ----
        {
            const u64t* ttc = (const u64t*)(sm + OFF_TTC);
            const u64t* tts = (const u64t*)(sm + OFF_TTS);
            for (int w = tid; w < 256; w += T) {
                int mp = w >> 3, q = w & 7;
                int m0 = mp*2, m1 = m0+1;
                const float* r0p = srp + (m0+3)*72 + 4;
                const float* r1p = srp + (m1+3)*72 + 4;   // m1==63 -> halo zeros
                u64t ar0=0,ar1=0,ar2=0,ar3=0, ai0=0,ai1=0,ai2=0,ai3=0;
                #pragma unroll 7
                for (int n = 0; n < 63; n++) {
                    u64t rp = pk2(r0p[n], r1p[n]);
                    const u64t* tc = ttc + n*32 + q*4;
                    const u64t* ts = tts + n*32 + q*4;
                    ulonglong2 c01 = *(const ulonglong2*)tc;
                    ulonglong2 c23 = *(const ulonglong2*)(tc + 2);
                    ulonglong2 s01 = *(const ulonglong2*)ts;
                    ulonglong2 s23 = *(const ulonglong2*)(ts + 2);
                    ar0 = ffma2(c01.x, rp, ar0);
                    ar1 = ffma2(c01.y, rp, ar1);
                    ar2 = ffma2(c23.x, rp, ar2);
                    ar3 = ffma2(c23.y, rp, ar3);
                    ai0 = ffma2(s01.x, rp, ai0);
                    ai1 = ffma2(s01.y, rp, ai1);
                    ai2 = ffma2(s23.x, rp, ai2);
                    ai3 = ffma2(s23.y, rp, ai3);
                }
                int k20 = q << 2;
                float2 v;
                v = upk2(ar0); sPr[(k20+0)*64+m0]=v.x*inv; sPr[(k20+0)*64+m1]=v.y*inv;
                v = upk2(ar1); sPr[(k20+1)*64+m0]=v.x*inv; sPr[(k20+1)*64+m1]=v.y*inv;
                v = upk2(ar2); sPr[(k20+2)*64+m0]=v.x*inv; sPr[(k20+2)*64+m1]=v.y*inv;
                v = upk2(ar3); sPr[(k20+3)*64+m0]=v.x*inv; sPr[(k20+3)*64+m1]=v.y*inv;
                v = upk2(ai0); sPi[(k20+0)*64+m0]=v.x*inv; sPi[(k20+0)*64+m1]=v.y*inv;
                v = upk2(ai1); sPi[(k20+1)*64+m0]=v.x*inv; sPi[(k20+1)*64+m1]=v.y*inv;
                v = upk2(ai2); sPi[(k20+2)*64+m0]=v.x*inv; sPi[(k20+2)*64+m1]=v.y*inv;
                v = upk2(ai3); sPi[(k20+3)*64+m0]=v.x*inv; sPi[(k20+3)*64+m1]=v.y*inv;
            }
        }
        __syncthreads();

        // ---- (C) C[k2][k1] = ((inv*sum_m conj(W[k1,m]) P[k2][m]) * wc); packed over m-pairs ----
        for (int w = tid; w < 512; w += T) {
            int k1 = w >> 3;
            if (k1 >= 63) continue;
            int q = w & 7, k20 = q << 2;
            int row0 = (k1 <= 32) ? k1 : 63-k1;
            float sg = (k1 <= 32) ? 1.f : -1.f;
            u64t arC[4]={0,0,0,0}, arS[4]={0,0,0,0}, aiC[4]={0,0,0,0}, aiS[4]={0,0,0,0};
            const u64t* mcp = (const u64t*)(smc + row0*64);
            const u64t* msp = (const u64t*)(sms + row0*64);
            #pragma unroll 4
            for (int mc = 0; mc < 16; mc++) {
                ulonglong2 cw = *(const ulonglong2*)(mcp + mc*2);
                ulonglong2 sw = *(const ulonglong2*)(msp + mc*2);
                #pragma unroll
                for (int kk = 0; kk < 4; kk++) {
                    ulonglong2 p  = *(const ulonglong2*)((const u64t*)(sPr + (k20+kk)*64) + mc*2);
                    ulonglong2 qi = *(const ulonglong2*)((const u64t*)(sPi + (k20+kk)*64) + mc*2);
                    arC[kk] = ffma2(cw.x, p.x,  arC[kk]); arC[kk] = ffma2(cw.y, p.y,  arC[kk]);
                    arS[kk] = ffma2(sw.x, qi.x, arS[kk]); arS[kk] = ffma2(sw.y, qi.y, arS[kk]);
                    aiC[kk] = ffma2(cw.x, qi.x, aiC[kk]); aiC[kk] = ffma2(cw.y, qi.y, aiC[kk]);
                    aiS[kk] = ffma2(sw.x, p.x,  aiS[kk]); aiS[kk] = ffma2(sw.y, p.y,  aiS[kk]);
                }
            }
            #pragma unroll
            for (int kk = 0; kk < 4; kk++) {
                int k2i = k20 + kk;
                float arv = (hadd2(arC[kk]) + sg*hadd2(arS[kk])) * inv;
                float aiv = (hadd2(aiC[kk]) - sg*hadd2(aiS[kk])) * inv;
                float wr = swcr[k1*32 + k2i], wi = swci[k1*32 + k2i];
                sCr[k2i*68 + k1] = arv*wr - aiv*wi;
                sCi[k2i*68 + k1] = arv*wi + aiv*wr;
            }
        }
        __syncthreads();

        // ---- (D) D[m][k2] = inv * sum_k1 W[m,k1] C[k2][k1]; packed over k1-pairs ----
        for (int w = tid; w < 512; w += T) {
            int m = w >> 3;
            if (m >= 63) continue;
            int q = w & 7, k20 = q << 2;
            int row0 = (m <= 32) ? m : 63-m;
            float sg = (m <= 32) ? 1.f : -1.f;
            u64t drC[4]={0,0,0,0}, drS[4]={0,0,0,0}, diC[4]={0,0,0,0}, diS[4]={0,0,0,0};
            const u64t* mcp = (const u64t*)(smc + row0*64);
            const u64t* msp = (const u64t*)(sms + row0*64);
            #pragma unroll 4
            for (int kc = 0; kc < 16; kc++) {
                ulonglong2 cw = *(const ulonglong2*)(mcp + kc*2);
                ulonglong2 sw = *(const ulonglong2*)(msp + kc*2);
                #pragma unroll
                for (int kk = 0; kk < 4; kk++) {
                    ulonglong2 cr = *(const ulonglong2*)((const u64t*)(sCr + (k20+kk)*68) + kc*2);
                    ulonglong2 ci = *(const ulonglong2*)((const u64t*)(sCi + (k20+kk)*68) + kc*2);
                    drC[kk] = ffma2(cw.x, cr.x, drC[kk]); drC[kk] = ffma2(cw.y, cr.y, drC[kk]);
                    drS[kk] = ffma2(sw.x, ci.x, drS[kk]); drS[kk] = ffma2(sw.y, ci.y, drS[kk]);
                    diC[kk] = ffma2(cw.x, ci.x, diC[kk]); diC[kk] = ffma2(cw.y, ci.y, diC[kk]);
                    diS[kk] = ffma2(sw.x, cr.x, diS[kk]); diS[kk] = ffma2(sw.y, cr.y, diS[kk]);
                }
            }
            #pragma unroll
            for (int kk = 0; kk < 4; kk++) {
                float dr = (hadd2(drC[kk]) - sg*hadd2(drS[kk])) * inv;
                float di = (hadd2(diC[kk]) + sg*hadd2(diS[kk])) * inv;
                sDr[m*32 + k20+kk] = dr;
                sDi[m*32 + k20+kk] = di;
            }
        }
        __syncthreads();

        // ---- (h) x[m,n] += inv*(Dr[m,0] + 2*sum_{k2=1..31} Re(D[m,k2] W[k2,n])) ----
        {
            const float4* mc4 = (const float4*)smc;
            const float4* ms4 = (const float4*)sms;
            for (int w = tid; w < 512; w += T) {
                int mp = w >> 4, g = w & 15;
                int m0 = mp*2, m1 = m0+1;
                int n0 = g << 2;
                const float* d0r = sDr + m0*32;
                const float* d0i = sDi + m0*32;
                const float* d1r = sDr + m1*32;
                const float* d1i = sDi + m1*32;
                bool do1 = (m1 < 63);
                float4 A0 = {0,0,0,0}, A1 = {0,0,0,0};
                #pragma unroll 8
                for (int k2 = 1; k2 < 32; k2++) {
                    float4 c = mc4[k2*16 + g];
                    float4 s = ms4[k2*16 + g];
                    float e0r = d0r[k2], e0i = d0i[k2];
                    A0.x += e0r*c.x - e0i*s.x;
                    A0.y += e0r*c.y - e0i*s.y;
                    A0.z += e0r*c.z - e0i*s.z;
                    A0.w += e0r*c.w - e0i*s.w;
                    if (do1) {
                        float e1r = d1r[k2], e1i = d1i[k2];
                        A1.x += e1r*c.x - e1i*s.x;
                        A1.y += e1r*c.y - e1i*s.y;
                        A1.z += e1r*c.z - e1i*s.z;
                        A1.w += e1r*c.w - e1i*s.w;
                    }
                }
                float base0 = d0r[0];
                float* xo0 = sxp + (m0+1)*68 + n0 + 1;
                xo0[0] += (base0 + 2.f*A0.x)*inv;
                xo0[1] += (base0 + 2.f*A0.y)*inv;
                xo0[2] += (base0 + 2.f*A0.z)*inv;
                if (g < 15) xo0[3] += (base0 + 2.f*A0.w)*inv;
                if (do1) {
                    float base1 = d1r[0];
                    float* xo1 = sxp + (m1+1)*68 + n0 + 1;
                    xo1[0] += (base1 + 2.f*A1.x)*inv;
                    xo1[1] += (base1 + 2.f*A1.y)*inv;
                    xo1[2] += (base1 + 2.f*A1.z)*inv;
                    if (g < 15) xo1[3] += (base1 + 2.f*A1.w)*inv;
                }
            }
        }
        __syncthreads();
    }

    // ---- final residual + sum of squares ----
    float loc = 0.f;
    #pragma unroll
    for (int p = 0; p < 8; p++) {
        int el = tid + p*T;
        if (el >= NP64) break;
        int i = el >> 6, j = el & 63;
        if (j >= 63) continue;
        const float* xb = sxp + i*68 + j;
        float acc = ska[0]*xb[0] + ska[1]*xb[1] + ska[2]*xb[2]
                  + ska[3]*xb[68] + ska[4]*xb[69] + ska[5]*xb[70]
                  + ska[6]*xb[136] + ska[7]*xb[137] + ska[8]*xb[138];
        float v = fr[p] - acc;
        loc += v * v;
    }
    #pragma unroll
    for (int off = 16; off; off >>= 1)
        loc += __shfl_xor_sync(0xFFFFFFFFu, loc, off);
    __shared__ float wsum[16];
    int wid = tid >> 5;
    if ((tid & 31) == 0) wsum[wid] = loc;
    __syncthreads();
    if (tid == 0) {
        float s = 0.f;
        #pragma unroll
        for (int w = 0; w < 16; w++) s += wsum[w];
        g_blocksum[b] = s;
    }
}

__global__ void final_reduce_kernel(float* __restrict__ out) {
    __shared__ float s[BATCH];
    s[threadIdx.x] = g_blocksum[threadIdx.x];
    __syncthreads();
    for (int st = BATCH/2; st > 0; st >>= 1) {
        if (threadIdx.x < st) s[threadIdx.x] += s[threadIdx.x + st];
        __syncthreads();
    }
    if (threadIdx.x == 0) out[0] = sqrtf(s[0]) / 256.0f;
}

// ---------------- host ----------------
extern "C" void kernel_launch(void* const* d_in, const int* in_sizes, int n_in,
                              void* d_out, int out_size) {
    const float* x      = (const float*)d_in[0];
    const float* f      = (const float*)d_in[1];
    const float* kA     = (const float*)d_in[2];
    const float* fc1_w1 = (const float*)d_in[3];
    const float* fc1_b1 = (const float*)d_in[4];
    const float* fc1_w2 = (const float*)d_in[5];
    const float* fc1_b2 = (const float*)d_in[6];
    const float* fc2_w1 = (const float*)d_in[7];
    const float* fc2_b1 = (const float*)d_in[8];
    const float* fc2_w2 = (const float*)d_in[9];
    const float* fc2_b2 = (const float*)d_in[10];
    const float* ct1_w  = (const float*)d_in[11];
    const float* ct1_b  = (const float*)d_in[12];
    const float* ct2_w  = (const float*)d_in[13];
    const float* ct2_b  = (const float*)d_in[14];
    const float* ct3_w  = (const float*)d_in[15];
    const float* ct3_b  = (const float*)d_in[16];
    const float* ct4_w  = (const float*)d_in[17];
    const float* ct4_b  = (const float*)d_in[18];
    const float* ct5_w  = (const float*)d_in[19];
    const float* ct5_b  = (const float*)d_in[20];
    float* out = (float*)d_out;

    cudaFuncSetAttribute(solver_kernel, cudaFuncAttributeMaxDynamicSharedMemorySize,
                         SMEM_FLOATS * (int)sizeof(float));

    init_tw_kernel<<<(63*64 + 255)/256, 256>>>();
    hyper_kernel<<<BATCH, 256>>>(kA, fc1_w1, fc1_b1, fc1_w2, fc1_b2,
                                 fc2_w1, fc2_b1, fc2_w2, fc2_b2);
    ct1_kernel<<<BATCH, 256>>>(kA, ct1_w, ct1_b);
    ct_mid_kernel<5> <<<dim3(BATCH, 4), 256>>>(g_a1, ct2_w, ct2_b, g_a2);
    ct_mid_kernel<9> <<<dim3(BATCH, 4), 256>>>(g_a2, ct3_w, ct3_b, g_a3);
    ct_mid_kernel<17><<<dim3(BATCH, 4), 256>>>(g_a3, ct4_w, ct4_b, g_a4);
    ct5_kernel<<<BATCH, 256>>>(ct5_w, ct5_b);
    solver_kernel<<<BATCH, 512, SMEM_FLOATS * sizeof(float)>>>(x, f, kA);
    final_reduce_kernel<<<1, BATCH>>>(out);
}

// round 6
// speedup vs baseline: 3.0441x; 3.0441x over previous
#include <cuda_runtime.h>
#include <math.h>

#define NN 63
#define NP (NN*NN)          // 3969
#define NP64 4032
#define BATCH 256
#define KS 7
#define ML 3

// ---------------- device scratch ----------------
__device__ float g_cosT[63*68];   // [k][n] rows padded to 68, cols 63..67 = 0
__device__ float g_sinT[63*68];
__device__ float g_w1[BATCH*147];
__device__ float g_w2[BATCH*147];
__device__ float g_a4[BATCH*1089*32];   // [b][pix][ch]
__device__ float g_blocksum[BATCH];

__device__ __forceinline__ float gelu_exact(float v) {
    return v * 0.5f * (1.0f + erff(v * 0.70710678118654752f));
}

__global__ void init_tw_kernel() {
    int idx = blockIdx.x * blockDim.x + threadIdx.x;
    if (idx < 63*68) {
        int k = idx / 68, n = idx % 68;
        if (n < 63) {
            float ang = 6.28318530717958647692f * (float)((k * n) % NN) / 63.0f;
            g_cosT[idx] = cosf(ang);
            g_sinT[idx] = sinf(ang);
        } else { g_cosT[idx] = 0.f; g_sinT[idx] = 0.f; }
    }
}

// ---------------- hypernet ----------------
__global__ void hyper_kernel(const float* __restrict__ kA,
                             const float* __restrict__ w1a, const float* __restrict__ b1a,
                             const float* __restrict__ w2a, const float* __restrict__ b2a,
                             const float* __restrict__ w1b, const float* __restrict__ b1b,
                             const float* __restrict__ w2b, const float* __restrict__ b2b) {
    int b = blockIdx.x;
    __shared__ float a[9], h1[100], h2[100];
    int t = threadIdx.x;
    if (t < 9) a[t] = kA[b*9 + t];
    __syncthreads();
    if (t < 100) {
        float s = b1a[t];
        #pragma unroll
        for (int i = 0; i < 9; i++) s += a[i] * w1a[i*100 + t];
        h1[t] = gelu_exact(s);
    } else if (t < 200) {
        int h = t - 100;
        float s = b1b[h];
        #pragma unroll
        for (int i = 0; i < 9; i++) s += a[i] * w1b[i*100 + h];
        h2[h] = gelu_exact(s);
    }
    __syncthreads();
    for (int o = t; o < 147; o += blockDim.x) {
        float s1 = b2a[o], s2 = b2b[o];
        for (int h = 0; h < 100; h++) {
            s1 += h1[h] * w2a[h*147 + o];
            s2 += h2[h] * w2b[h*147 + o];
        }
        g_w1[b*147 + o] = s1;
        g_w2[b*147 + o] = s2;
    }
}

// ---------------- fused ConvTranspose chain ct1..ct4 (one block per sample) ----------------
// smem: s_w 9360 | B1 9248 | B2 2592 | s_a 16 | s_bias 32  = 21248 floats

__device__ __forceinline__ void load_ctw(const float* __restrict__ w,
                                         const float* __restrict__ bias,
                                         float* s_w, float* s_bias, int tid) {
    for (int idx = tid; idx < 9216; idx += 512) {
        int i = idx & 31, o = (idx >> 5) & 31, k = idx >> 10;
        s_w[k*1040 + (o>>3)*260 + (o&7)*32 + i] = w[(i*32 + o)*9 + k];
    }
    if (tid < 32) s_bias[tid] = bias[tid];
}

template<int IN_H>
__device__ void ct_midstage(const float* __restrict__ s_in, const float* __restrict__ s_w,
                            const float* __restrict__ s_bias, float* __restrict__ out, int tid) {
    constexpr int OUT_H = 2*IN_H - 1;
    constexpr int OUT_SZ = OUT_H*OUT_H;
    const float4* in4 = (const float4*)s_in;
    const float4* w4  = (const float4*)s_w;
    for (int it = tid; it < OUT_SZ*4; it += 512) {
        int pix = it >> 2, og = it & 3;
        int y = pix / OUT_H, x = pix % OUT_H;
        float acc[8];
        #pragma unroll
        for (int ol = 0; ol < 8; ol++) acc[ol] = s_bias[og*8 + ol];
        int kys[2], iys[2], nky, kxs[2], ixs[2], nkx;
        if (y & 1) { nky=2; kys[0]=0; iys[0]=(y+1)>>1; kys[1]=2; iys[1]=(y-1)>>1; }
        else       { nky=1; kys[0]=1; iys[0]=y>>1; }
        if (x & 1) { nkx=2; kxs[0]=0; ixs[0]=(x+1)>>1; kxs[1]=2; ixs[1]=(x-1)>>1; }
        else       { nkx=1; kxs[0]=1; ixs[0]=x>>1; }
        for (int p = 0; p < nky; p++)
            for (int q = 0; q < nkx; q++) {
                int base4 = (iys[p]*IN_H + ixs[q]) * 8;
                const float4* wrow = w4 + (kys[p]*3 + kxs[q])*260 + og*65;
                #pragma unroll
                for (int c4 = 0; c4 < 8; c4++) {
                    float4 v = in4[base4 + c4];
                    #pragma unroll
                    for (int ol = 0; ol < 8; ol++) {
                        float4 wv = wrow[ol*8 + c4];
                        acc[ol] += v.x*wv.x + v.y*wv.y + v.z*wv.z + v.w*wv.w;
                    }
                }
            }
        float* ob = out + pix*32 + og*8;
        float4 o0 = {gelu_exact(acc[0]), gelu_exact(acc[1]), gelu_exact(acc[2]), gelu_exact(acc[3])};
        float4 o1 = {gelu_exact(acc[4]), gelu_exact(acc[5]), gelu_exact(acc[6]), gelu_exact(acc[7])};
        *(float4*)ob = o0;
        *(float4*)(ob + 4) = o1;
    }
}

__global__ void __launch_bounds__(512) ctchain_kernel(
    const float* __restrict__ kA,
    const float* __restrict__ w1c, const float* __restrict__ b1c,
    const float* __restrict__ w2c, const float* __restrict__ b2c,
    const float* __restrict__ w3c, const float* __restrict__ b3c,
    const float* __restrict__ w4c, const float* __restrict__ b4c) {
    extern __shared__ float cs[];
    float* s_w    = cs;               // 9360
    float* B1     = cs + 9360;        // 9248
    float* B2     = B1 + 9248;        // 2592
    float* s_a    = B2 + 2592;        // 16
    float* s_bias = s_a + 16;         // 32
    int b = blockIdx.x, tid = threadIdx.x;

    if (tid < 9) s_a[tid] = kA[b*9 + tid];
    load_ctw(w2c, b2c, s_w, s_bias, tid);
    __syncthreads();

    // ct1: 3x3 -> 5x5, 32ch, gelu -> B1 [25][32]
    for (int el = tid; el < 800; el += 512) {
        int pix = el >> 5, o = el & 31;
        int y = pix / 5, x = pix % 5;
        float acc = b1c[o];
        int kys[2], iys[2], nky, kxs[2], ixs[2], nkx;
        if (y & 1) { nky=2; kys[0]=0; iys[0]=(y+1)>>1; kys[1]=2; iys[1]=(y-1)>>1; }
        else       { nky=1; kys[0]=1; iys[0]=y>>1; }
        if (x & 1) { nkx=2; kxs[0]=0; ixs[0]=(x+1)>>1; kxs[1]=2; ixs[1]=(x-1)>>1; }
        else       { nkx=1; kxs[0]=1; ixs[0]=x>>1; }
        for (int p = 0; p < nky; p++)
            for (int q = 0; q < nkx; q++)
                acc += s_a[iys[p]*3 + ixs[q]] * w1c[o*9 + kys[p]*3 + kxs[q]];
        B1[pix*32 + o] = gelu_exact(acc);
    }
    __syncthreads();

    ct_midstage<5>(B1, s_w, s_bias, B2, tid);        // 5 -> 9 into B2
    __syncthreads();
    load_ctw(w3c, b3c, s_w, s_bias, tid);
    __syncthreads();
    ct_midstage<9>(B2, s_w, s_bias, B1, tid);        // 9 -> 17 into B1
    __syncthreads();
    load_ctw(w4c, b4c, s_w, s_bias, tid);
    __syncthreads();
    ct_midstage<17>(B1, s_w, s_bias, g_a4 + (size_t)b*1089*32, tid);  // 17 -> 33 to global
}

// ---------------- persistent per-sample solver ----------------
// padded strides: twiddle/S rows 68, D/wc rows 36 (stride mod 32 = 4 -> conflict-free)
#define O_SXP 0                      // 65x68 = 4420
#define O_SRP 4420                   // 69x72 = 4968
#define O_T   9388                   // 3*4968 = 14904 (also h-staging 7938)
#define O_SR  24292                  // 63x68 = 4284
#define O_SI  28576
#define O_CR  32860                  // 63x32 = 2016
#define O_CI  34876
#define O_DR  36892                  // 63x36 = 2268
#define O_DI  39160
#define O_WCR 41428                  // 63x36 = 2268
#define O_WCI 43696
#define O_CT  45964                  // 63x68 = 4284
#define O_ST  50248
#define O_W5  54532                  // 576
#define O_W1  55108                  // 160
#define O_W2  55268
#define O_KA  55428
#define SMEM_FLOATS 55444            // 221776 B

__global__ void __launch_bounds__(512) solver_kernel(const float* __restrict__ x_in,
                              const float* __restrict__ f_in,
                              const float* __restrict__ kA,
                              const float* __restrict__ w5, const float* __restrict__ b5) {
    extern __shared__ float sm[];
    float* sxp  = sm + O_SXP;
    float* srp  = sm + O_SRP;
    float* sT   = sm + O_T;
    float* sSr  = sm + O_SR;
    float* sSi  = sm + O_SI;
    float* sCr  = sm + O_CR;
    float* sCi  = sm + O_CI;
    float* sDr  = sm + O_DR;
    float* sDi  = sm + O_DI;
    float* swcr = sm + O_WCR;
    float* swci = sm + O_WCI;
    float* sct  = sm + O_CT;
    float* sst  = sm + O_ST;
    float* sw5  = sm + O_W5;
    float* sw1  = sm + O_W1;
    float* sw2  = sm + O_W2;
    float* ska  = sm + O_KA;

    int b = blockIdx.x, tid = threadIdx.x;
    const int T = 512;
    const float inv = 0.12598815766974242f;  // 1/sqrt(63)

    // ---- init ----
    float fr[8];
    #pragma unroll
    for (int p = 0; p < 8; p++) {
        int el = tid + p*T;
        fr[p] = 0.f;
        if (el < NP64) {
            int i = el >> 6, j = el & 63;
            if (j < 63) {
                fr[p] = f_in[b*NP + i*NN + j];
                sxp[(i+1)*68 + (j+1)] = x_in[b*NP + i*NN + j];
            }
        }
    }
    for (int el = tid; el < 63*68; el += T) { sct[el] = g_cosT[el]; sst[el] = g_sinT[el]; }
    for (int c = tid; c < 65; c += T) {
        sxp[c] = (c == 64) ? 1.f : 0.f;
        sxp[64*68 + c] = 1.f;
    }
    for (int r = tid; r < 65; r += T) {
        sxp[r*68] = (r == 64) ? 1.f : 0.f;
        sxp[r*68 + 64] = 1.f;
    }
    // ct5 weights: [32][2][3][3] -> s_w5[k*64 + o*32 + i]
    for (int idx = tid; idx < 576; idx += T) {
        int k = idx / 64, r = idx & 63, o = r >> 5, i = r & 31;
        sw5[idx] = w5[i*18 + o*9 + k];
    }
    if (tid < 9) ska[tid] = kA[b*9 + tid];
    for (int el = tid; el < 147; el += T) {
        sw1[el] = g_w1[b*147 + el];
        sw2[el] = g_w2[b*147 + el];
    }
    __syncthreads();

    // ---- ct5 fused: h flat [2][63*63] into sT staging ----
    {
        float b0 = b5[0], b1 = b5[1];
        const float4* s_w4 = (const float4*)sw5;
        const float4* gin = (const float4*)(g_a4 + (size_t)b * 1089 * 32);
        for (int pix = tid; pix < NP; pix += T) {
            int y = pix / NN, x = pix % NN;
            float acc0 = b0, acc1 = b1;
            int kys[2], iys[2], nky, kxs[2], ixs[2], nkx;
            if (y & 1) { nky=1; kys[0]=1; iys[0]=(y+1)>>1; }
            else       { nky=2; kys[0]=0; iys[0]=(y+2)>>1; kys[1]=2; iys[1]=y>>1; }
            if (x & 1) { nkx=1; kxs[0]=1; ixs[0]=(x+1)>>1; }
            else       { nkx=2; kxs[0]=0; ixs[0]=(x+2)>>1; kxs[1]=2; ixs[1]=x>>1; }
            for (int p = 0; p < nky; p++)
                for (int q = 0; q < nkx; q++) {
                    int base4 = (iys[p]*33 + ixs[q]) * 8;
                    int kk = kys[p]*3 + kxs[q];
                    #pragma unroll
                    for (int c4 = 0; c4 < 8; c4++) {
                        float4 v = __ldg(gin + base4 + c4);
                        float4 w0 = s_w4[kk*16 + c4];
                        float4 w1 = s_w4[kk*16 + 8 + c4];
                        acc0 += v.x*w0.x + v.y*w0.y + v.z*w0.z + v.w*w0.w;
                        acc1 += v.x*w1.x + v.y*w1.y + v.z*w1.z + v.w*w1.w;
                    }
                }
            sT[pix] = acc0;
            sT[NP + pix] = acc1;
        }
    }
    __syncthreads();
    // scatter raw-reinterp complex weights: wc[k1][k2] = (flat[2p], flat[2p+1]), p=k1*63+k2, k2<32
    for (int el = tid; el < 2016; el += T) {
        int k1 = el >> 5, k2 = el & 31;
        int p = k1*63 + k2;
        swcr[k1*36 + k2] = sT[2*p];
        swci[k1*36 + k2] = sT[2*p + 1];
    }
    __syncthreads();
    for (int el = tid; el < 14904; el += T) sT[el] = 0.f;
    for (int el = tid; el < 4968; el += T) srp[el] = 0.f;
    __syncthreads();

    for (int iter = 0; iter < 5; iter++) {
        // ---- (a) residual -> srp ----
        #pragma unroll
        for (int p = 0; p < 8; p++) {
            int el = tid + p*T;
            if (el >= NP64) break;
            int i = el >> 6, j = el & 63;
            if (j >= 63) continue;
            const float* xb = sxp + i*68 + j;
            float acc = ska[0]*xb[0] + ska[1]*xb[1] + ska[2]*xb[2]
                      + ska[3]*xb[68] + ska[4]*xb[69] + ska[5]*xb[70]
                      + ska[6]*xb[136] + ska[7]*xb[137] + ska[8]*xb[138];
            srp[(i+3)*72 + j + 4] = fr[p] - acc;
        }
        __syncthreads();

        // ---- (b) stage1: t[c] = conv7(r, w1[c]) — 3 channels, read r once ----
        for (int w = tid; w < 1024; w += T) {
            int i = w >> 4, g = w & 15;
            if (i >= 63) continue;
            int j0 = g << 2;
            float4 A0 = {0,0,0,0}, A1 = {0,0,0,0}, A2 = {0,0,0,0};
            #pragma unroll
            for (int u = 0; u < 7; u++) {
                const float4* rp = (const float4*)(srp + (i+u)*72 + j0);
                float4 Ra = rp[0], Rb = rp[1], Rc = rp[2];
                float rr[12] = {Ra.x,Ra.y,Ra.z,Ra.w, Rb.x,Rb.y,Rb.z,Rb.w, Rc.x,Rc.y,Rc.z,Rc.w};
                #pragma unroll
                for (int v = 0; v < 7; v++) {
                    float w0 = sw1[u*7 + v];
                    float w1 = sw1[49 + u*7 + v];
                    float w2 = sw1[98 + u*7 + v];
                    A0.x += rr[v+1]*w0; A0.y += rr[v+2]*w0; A0.z += rr[v+3]*w0; A0.w += rr[v+4]*w0;
                    A1.x += rr[v+1]*w1; A1.y += rr[v+2]*w1; A1.z += rr[v+3]*w1; A1.w += rr[v+4]*w1;
                    A2.x += rr[v+1]*w2; A2.y += rr[v+2]*w2; A2.z += rr[v+3]*w2; A2.w += rr[v+4]*w2;
                }
            }
            float* o0 = sT + (i+3)*72 + j0 + 4;
            float* o1 = o0 + 4968;
            float* o2 = o1 + 4968;
            if (g < 15) {
                *(float4*)o0 = A0; *(float4*)o1 = A1; *(float4*)o2 = A2;
            } else {
                o0[0]=A0.x; o0[1]=A0.y; o0[2]=A0.z;
                o1[0]=A1.x; o1[1]=A1.y; o1[2]=A1.z;
                o2[0]=A2.x; o2[1]=A2.y; o2[2]=A2.z;
            }
        }
        __syncthreads();

        // ---- (c) stage2: x += sum_c conv7(t[c], w2[c]) ----
        for (int w = tid; w < 1024; w += T) {
            int i = w >> 4, g = w & 15;
            if (i >= 63) continue;
            int j0 = g << 2;
            float a0=0.f, a1=0.f, a2=0.f, a3=0.f;
            #pragma unroll
            for (int c = 0; c < 3; c++) {
                const float* tb = sT + c*4968;
                const float* wc_ = sw2 + c*49;
                #pragma unroll
                for (int u = 0; u < 7; u++) {
                    const float4* rp = (const float4*)(tb + (i+u)*72 + j0);
                    float4 Ra = rp[0], Rb = rp[1], Rc = rp[2];
                    float rr[12] = {Ra.x,Ra.y,Ra.z,Ra.w, Rb.x,Rb.y,Rb.z,Rb.w, Rc.x,Rc.y,Rc.z,Rc.w};
                    #pragma unroll
                    for (int v = 0; v < 7; v++) {
                        float wv = wc_[u*7 + v];
                        a0 += rr[v+1]*wv; a1 += rr[v+2]*wv;
                        a2 += rr[v+3]*wv; a3 += rr[v+4]*wv;
                    }
                }
            }
            float* xo = sxp + (i+1)*68 + j0 + 1;
            xo[0] += a0; xo[1] += a1; xo[2] += a2;
            if (g < 15) xo[3] += a3;
        }
        __syncthreads();

        // ---- (d) residual -> srp ----
        #pragma unroll
        for (int p = 0; p < 8; p++) {
            int el = tid + p*T;
            if (el >= NP64) break;
            int i = el >> 6, j = el & 63;
            if (j >= 63) continue;
            const float* xb = sxp + i*68 + j;
            float acc = ska[0]*xb[0] + ska[1]*xb[1] + ska[2]*xb[2]
                      + ska[3]*xb[68] + ska[4]*xb[69] + ska[5]*xb[70]
                      + ska[6]*xb[136] + ska[7]*xb[137] + ska[8]*xb[138];
            srp[(i+3)*72 + j + 4] = fr[p] - acc;
        }
        __syncthreads();

        // ---- (e) S[k1,n] = inv * sum_m conj(W[k1,m]) r[m,n] ----
        for (int w = tid; w < 1024; w += T) {
            int k1 = w >> 4, g = w & 15;
            if (k1 >= 63) continue;
            const float* cT = sct + k1*68;
            const float* sT_ = sst + k1*68;
            float arx=0,ary=0,arz=0,arw=0, aix=0,aiy=0,aiz=0,aiw=0;
            #pragma unroll 9
            for (int m = 0; m < 63; m++) {
                float c = cT[m], s = sT_[m];
                float4 rv = *(const float4*)(srp + (m+3)*72 + 4 + (g<<2));
                arx += c*rv.x; ary += c*rv.y; arz += c*rv.z; arw += c*rv.w;
                aix -= s*rv.x; aiy -= s*rv.y; aiz -= s*rv.z; aiw -= s*rv.w;
            }
            float4 R = {arx*inv, ary*inv, arz*inv, arw*inv};
            float4 I = {aix*inv, aiy*inv, aiz*inv, aiw*inv};
            *(float4*)(sSr + k1*68 + (g<<2)) = R;
            *(float4*)(sSi + k1*68 + (g<<2)) = I;
        }
        __syncthreads();

        // ---- (f) C[k1,k2] = (inv * sum_n S[k1,n] conj(W[k2,n])) * wc  (k2<32) ----
        for (int w = tid; w < 512; w += T) {
            if (w >= 504) continue;
            int k1 = w >> 3, kg = w & 7, k20 = kg << 2;
            const float* srow = sSr + k1*68;
            const float* sirow = sSi + k1*68;
            float arx=0,ary=0,arz=0,arw=0, aix=0,aiy=0,aiz=0,aiw=0;
            #pragma unroll 9
            for (int n = 0; n < 63; n++) {
                float a = srow[n], bI = sirow[n];
                float4 c4 = *(const float4*)(sct + n*68 + k20);   // W[n][k2] = W[k2][n]
                float4 s4 = *(const float4*)(sst + n*68 + k20);
                arx += a*c4.x + bI*s4.x;  aix += bI*c4.x - a*s4.x;
                ary += a*c4.y + bI*s4.y;  aiy += bI*c4.y - a*s4.y;
                arz += a*c4.z + bI*s4.z;  aiz += bI*c4.z - a*s4.z;
                arw += a*c4.w + bI*s4.w;  aiw += bI*c4.w - a*s4.w;
            }
            float4 wr = *(const float4*)(swcr + k1*36 + k20);
            float4 wi = *(const float4*)(swci + k1*36 + k20);
            arx*=inv; ary*=inv; arz*=inv; arw*=inv;
            aix*=inv; aiy*=inv; aiz*=inv; aiw*=inv;
            float4 cr = {arx*wr.x - aix*wi.x, ary*wr.y - aiy*wi.y,
                         arz*wr.z - aiz*wi.z, arw*wr.w - aiw*wi.w};
            float4 ci = {arx*wi.x + aix*wr.x, ary*wi.y + aiy*wr.y,
                         arz*wi.z + aiz*wr.z, arw*wi.w + aiw*wr.w};
            *(float4*)(sCr + k1*32 + k20) = cr;
            *(float4*)(sCi + k1*32 + k20) = ci;
        }
        __syncthreads();

        // ---- (g) D[m,k2] = inv * sum_k1 W[m,k1] C[k1,k2] ----
        for (int w = tid; w < 2016; w += T) {
            int m = w >> 5, k2 = w & 31;
            const float4* cR = (const float4*)(sct + m*68);
            const float4* sR = (const float4*)(sst + m*68);
            float ar = 0.f, ai = 0.f;
            #pragma unroll 4
            for (int kc = 0; kc < 16; kc++) {
                float4 c4 = cR[kc], s4 = sR[kc];
                int k1 = kc << 2;
                float cr0 = sCr[(k1+0)*32+k2], ci0 = sCi[(k1+0)*32+k2];
                float cr1 = sCr[(k1+1)*32+k2], ci1 = sCi[(k1+1)*32+k2];
                float cr2 = sCr[(k1+2)*32+k2], ci2 = sCi[(k1+2)*32+k2];
                float cr3 = sCr[(k1+3)*32+k2], ci3 = sCi[(k1+3)*32+k2];
                // k1=63 tap multiplied by c4.w/s4.w = 0 (padded cols) — safe in-smem OOB read
                ar += c4.x*cr0 - s4.x*ci0;  ai += c4.x*ci0 + s4.x*cr0;
                ar += c4.y*cr1 - s4.y*ci1;  ai += c4.y*ci1 + s4.y*cr1;
                ar += c4.z*cr2 - s4.z*ci2;  ai += c4.z*ci2 + s4.z*cr2;
                ar += c4.w*cr3 - s4.w*ci3;  ai += c4.w*ci3 + s4.w*cr3;
            }
            sDr[m*36 + k2] = ar * inv;
            sDi[m*36 + k2] = ai * inv;
        }
        __syncthreads();

        // ---- (h) x[m,n] += inv*(Dr[m,0] + 2*sum_{k2=1..31} Re(D[m,k2] W[k2,n])) ----
        for (int w = tid; w < 1024; w += T) {
            int m = w >> 4, g = w & 15;
            if (m >= 63) continue;
            int n0 = g << 2;
            const float* dr_ = sDr + m*36;
            const float* di_ = sDi + m*36;
            float d0 = dr_[0];
            float ax=d0, ay=d0, az=d0, aw=d0;
            #pragma unroll 8
            for (int k2 = 1; k2 < 32; k2++) {
                float dr2 = dr_[k2]*2.f, di2 = di_[k2]*2.f;
                float4 c4 = *(const float4*)(sct + k2*68 + n0);
                float4 s4 = *(const float4*)(sst + k2*68 + n0);
                ax += dr2*c4.x - di2*s4.x;
                ay += dr2*c4.y - di2*s4.y;
                az += dr2*c4.z - di2*s4.z;
                aw += dr2*c4.w - di2*s4.w;
            }
            float* xo = sxp + (m+1)*68 + n0 + 1;
            xo[0] += ax*inv; xo[1] += ay*inv; xo[2] += az*inv;
            if (g < 15) xo[3] += aw*inv;
        }
        __syncthreads();
    }

    // ---- final residual + sum of squares ----
    float loc = 0.f;
    #pragma unroll
    for (int p = 0; p < 8; p++) {
        int el = tid + p*T;
        if (el >= NP64) break;
        int i = el >> 6, j = el & 63;
        if (j >= 63) continue;
        const float* xb = sxp + i*68 + j;
        float acc = ska[0]*xb[0] + ska[1]*xb[1] + ska[2]*xb[2]
                  + ska[3]*xb[68] + ska[4]*xb[69] + ska[5]*xb[70]
                  + ska[6]*xb[136] + ska[7]*xb[137] + ska[8]*xb[138];
        float v = fr[p] - acc;
        loc += v * v;
    }
    #pragma unroll
    for (int off = 16; off; off >>= 1)
        loc += __shfl_xor_sync(0xFFFFFFFFu, loc, off);
    __shared__ float wsum[16];
    int wid = tid >> 5;
    if ((tid & 31) == 0) wsum[wid] = loc;
    __syncthreads();
    if (tid == 0) {
        float s = 0.f;
        #pragma unroll
        for (int w = 0; w < 16; w++) s += wsum[w];
        g_blocksum[b] = s;
    }
}

__global__ void final_reduce_kernel(float* __restrict__ out) {
    __shared__ float s[BATCH];
    s[threadIdx.x] = g_blocksum[threadIdx.x];
    __syncthreads();
    for (int st = BATCH/2; st > 0; st >>= 1) {
        if (threadIdx.x < st) s[threadIdx.x] += s[threadIdx.x + st];
        __syncthreads();
    }
    if (threadIdx.x == 0) out[0] = sqrtf(s[0]) / 256.0f;
}

// ---------------- host ----------------
extern "C" void kernel_launch(void* const* d_in, const int* in_sizes, int n_in,
                              void* d_out, int out_size) {
    const float* x      = (const float*)d_in[0];
    const float* f      = (const float*)d_in[1];
    const float* kA     = (const float*)d_in[2];
    const float* fc1_w1 = (const float*)d_in[3];
    const float* fc1_b1 = (const float*)d_in[4];
    const float* fc1_w2 = (const float*)d_in[5];
    const float* fc1_b2 = (const float*)d_in[6];
    const float* fc2_w1 = (const float*)d_in[7];
    const float* fc2_b1 = (const float*)d_in[8];
    const float* fc2_w2 = (const float*)d_in[9];
    const float* fc2_b2 = (const float*)d_in[10];
    const float* ct1_w  = (const float*)d_in[11];
    const float* ct1_b  = (const float*)d_in[12];
    const float* ct2_w  = (const float*)d_in[13];
    const float* ct2_b  = (const float*)d_in[14];
    const float* ct3_w  = (const float*)d_in[15];
    const float* ct3_b  = (const float*)d_in[16];
    const float* ct4_w  = (const float*)d_in[17];
    const float* ct4_b  = (const float*)d_in[18];
    const float* ct5_w  = (const float*)d_in[19];
    const float* ct5_b  = (const float*)d_in[20];
    float* out = (float*)d_out;

    cudaFuncSetAttribute(solver_kernel, cudaFuncAttributeMaxDynamicSharedMemorySize,
                         SMEM_FLOATS * (int)sizeof(float));
    cudaFuncSetAttribute(ctchain_kernel, cudaFuncAttributeMaxDynamicSharedMemorySize,
                         21248 * (int)sizeof(float));

    hyper_kernel<<<BATCH, 256>>>(kA, fc1_w1, fc1_b1, fc1_w2, fc1_b2,
                                 fc2_w1, fc2_b1, fc2_w2, fc2_b2);
    ctchain_kernel<<<BATCH, 512, 21248 * sizeof(float)>>>(kA, ct1_w, ct1_b, ct2_w, ct2_b,
                                                          ct3_w, ct3_b, ct4_w, ct4_b);
    init_tw_kernel<<<(63*68 + 255)/256, 256>>>();
    solver_kernel<<<BATCH, 512, SMEM_FLOATS * sizeof(float)>>>(x, f, kA, ct5_w, ct5_b);
    final_reduce_kernel<<<1, BATCH>>>(out);
}

// round 7
// speedup vs baseline: 3.3002x; 1.0841x over previous
#include <cuda_runtime.h>
#include <math.h>

#define NN 63
#define NP (NN*NN)          // 3969
#define NP64 4032
#define BATCH 256
#define KS 7
#define ML 3

// ---------------- device scratch ----------------
__device__ float g_cosT[63*68];   // [k][n] rows padded to 68, cols 63..67 = 0
__device__ float g_sinT[63*68];
__device__ float g_cosTT[63*36];  // transposed [n][k2<32], stride 36
__device__ float g_sinTT[63*36];
__device__ float g_w1[BATCH*147];
__device__ float g_w2[BATCH*147];
__device__ float g_a4[BATCH*1089*32];   // [b][pix][ch]
__device__ float g_blocksum[BATCH];

__device__ __forceinline__ float gelu_exact(float v) {
    return v * 0.5f * (1.0f + erff(v * 0.70710678118654752f));
}

__global__ void init_tw_kernel() {
    int idx = blockIdx.x * blockDim.x + threadIdx.x;
    if (idx < 63*68) {
        int k = idx / 68, n = idx % 68;
        if (n < 63) {
            float ang = 6.28318530717958647692f * (float)((k * n) % NN) / 63.0f;
            g_cosT[idx] = cosf(ang);
            g_sinT[idx] = sinf(ang);
        } else { g_cosT[idx] = 0.f; g_sinT[idx] = 0.f; }
    }
    if (idx < 63*36) {
        int n = idx / 36, k2 = idx % 36;
        if (k2 < 32) {
            float ang = 6.28318530717958647692f * (float)((k2 * n) % NN) / 63.0f;
            g_cosTT[idx] = cosf(ang);
            g_sinTT[idx] = sinf(ang);
        } else { g_cosTT[idx] = 0.f; g_sinTT[idx] = 0.f; }
    }
}

// ---------------- hypernet ----------------
__global__ void hyper_kernel(const float* __restrict__ kA,
                             const float* __restrict__ w1a, const float* __restrict__ b1a,
                             const float* __restrict__ w2a, const float* __restrict__ b2a,
                             const float* __restrict__ w1b, const float* __restrict__ b1b,
                             const float* __restrict__ w2b, const float* __restrict__ b2b) {
    int b = blockIdx.x;
    __shared__ float a[9], h1[100], h2[100];
    int t = threadIdx.x;
    if (t < 9) a[t] = kA[b*9 + t];
    __syncthreads();
    if (t < 100) {
        float s = b1a[t];
        #pragma unroll
        for (int i = 0; i < 9; i++) s += a[i] * w1a[i*100 + t];
        h1[t] = gelu_exact(s);
    } else if (t < 200) {
        int h = t - 100;
        float s = b1b[h];
        #pragma unroll
        for (int i = 0; i < 9; i++) s += a[i] * w1b[i*100 + h];
        h2[h] = gelu_exact(s);
    }
    __syncthreads();
    for (int o = t; o < 147; o += blockDim.x) {
        float s1 = b2a[o], s2 = b2b[o];
        for (int h = 0; h < 100; h++) {
            s1 += h1[h] * w2a[h*147 + o];
            s2 += h2[h] * w2b[h*147 + o];
        }
        g_w1[b*147 + o] = s1;
        g_w2[b*147 + o] = s2;
    }
}

// ---------------- fused ConvTranspose chain ct1..ct4 ----------------
__device__ __forceinline__ void load_ctw(const float* __restrict__ w,
                                         const float* __restrict__ bias,
                                         float* s_w, float* s_bias, int tid) {
    for (int idx = tid; idx < 9216; idx += 512) {
        int i = idx & 31, o = (idx >> 5) & 31, k = idx >> 10;
        s_w[k*1040 + (o>>3)*260 + (o&7)*32 + i] = w[(i*32 + o)*9 + k];
    }
    if (tid < 32) s_bias[tid] = bias[tid];
}

template<int IN_H>
__device__ void ct_midstage(const float* __restrict__ s_in, const float* __restrict__ s_w,
                            const float* __restrict__ s_bias, float* __restrict__ out, int tid) {
    constexpr int OUT_H = 2*IN_H - 1;
    constexpr int OUT_SZ = OUT_H*OUT_H;
    const float4* in4 = (const float4*)s_in;
    const float4* w4  = (const float4*)s_w;
    for (int it = tid; it < OUT_SZ*4; it += 512) {
        int pix = it >> 2, og = it & 3;
        int y = pix / OUT_H, x = pix % OUT_H;
        float acc[8];
        #pragma unroll
        for (int ol = 0; ol < 8; ol++) acc[ol] = s_bias[og*8 + ol];
        int kys[2], iys[2], nky, kxs[2], ixs[2], nkx;
        if (y & 1) { nky=2; kys[0]=0; iys[0]=(y+1)>>1; kys[1]=2; iys[1]=(y-1)>>1; }
        else       { nky=1; kys[0]=1; iys[0]=y>>1; }
        if (x & 1) { nkx=2; kxs[0]=0; ixs[0]=(x+1)>>1; kxs[1]=2; ixs[1]=(x-1)>>1; }
        else       { nkx=1; kxs[0]=1; ixs[0]=x>>1; }
        for (int p = 0; p < nky; p++)
            for (int q = 0; q < nkx; q++) {
                int base4 = (iys[p]*IN_H + ixs[q]) * 8;
                const float4* wrow = w4 + (kys[p]*3 + kxs[q])*260 + og*65;
                #pragma unroll
                for (int c4 = 0; c4 < 8; c4++) {
                    float4 v = in4[base4 + c4];
                    #pragma unroll
                    for (int ol = 0; ol < 8; ol++) {
                        float4 wv = wrow[ol*8 + c4];
                        acc[ol] += v.x*wv.x + v.y*wv.y + v.z*wv.z + v.w*wv.w;
                    }
                }
            }
        float* ob = out + pix*32 + og*8;
        float4 o0 = {gelu_exact(acc[0]), gelu_exact(acc[1]), gelu_exact(acc[2]), gelu_exact(acc[3])};
        float4 o1 = {gelu_exact(acc[4]), gelu_exact(acc[5]), gelu_exact(acc[6]), gelu_exact(acc[7])};
        *(float4*)ob = o0;
        *(float4*)(ob + 4) = o1;
    }
}

__global__ void __launch_bounds__(512) ctchain_kernel(
    const float* __restrict__ kA,
    const float* __restrict__ w1c, const float* __restrict__ b1c,
    const float* __restrict__ w2c, const float* __restrict__ b2c,
    const float* __restrict__ w3c, const float* __restrict__ b3c,
    const float* __restrict__ w4c, const float* __restrict__ b4c) {
    extern __shared__ float cs[];
    float* s_w    = cs;               // 9360
    float* B1     = cs + 9360;        // 9248
    float* B2     = B1 + 9248;        // 2592
    float* s_a    = B2 + 2592;        // 16
    float* s_bias = s_a + 16;         // 32
    int b = blockIdx.x, tid = threadIdx.x;

    if (tid < 9) s_a[tid] = kA[b*9 + tid];
    load_ctw(w2c, b2c, s_w, s_bias, tid);
    __syncthreads();

    for (int el = tid; el < 800; el += 512) {
        int pix = el >> 5, o = el & 31;
        int y = pix / 5, x = pix % 5;
        float acc = b1c[o];
        int kys[2], iys[2], nky, kxs[2], ixs[2], nkx;
        if (y & 1) { nky=2; kys[0]=0; iys[0]=(y+1)>>1; kys[1]=2; iys[1]=(y-1)>>1; }
        else       { nky=1; kys[0]=1; iys[0]=y>>1; }
        if (x & 1) { nkx=2; kxs[0]=0; ixs[0]=(x+1)>>1; kxs[1]=2; ixs[1]=(x-1)>>1; }
        else       { nkx=1; kxs[0]=1; ixs[0]=x>>1; }
        for (int p = 0; p < nky; p++)
            for (int q = 0; q < nkx; q++)
                acc += s_a[iys[p]*3 + ixs[q]] * w1c[o*9 + kys[p]*3 + kxs[q]];
        B1[pix*32 + o] = gelu_exact(acc);
    }
    __syncthreads();

    ct_midstage<5>(B1, s_w, s_bias, B2, tid);
    __syncthreads();
    load_ctw(w3c, b3c, s_w, s_bias, tid);
    __syncthreads();
    ct_midstage<9>(B2, s_w, s_bias, B1, tid);
    __syncthreads();
    load_ctw(w4c, b4c, s_w, s_bias, tid);
    __syncthreads();
    ct_midstage<17>(B1, s_w, s_bias, g_a4 + (size_t)b*1089*32, tid);
}

// ---------------- persistent per-sample solver ----------------
#define O_SXP 0                      // 65x68 = 4420
#define O_SRP 4420                   // 69x72 = 4968
#define O_T   9388                   // 3*4968 = 14904 (ct5 staging 7938 fits)
#define O_PR  24292                  // [m][36] = 2268
#define O_PI  26560
#define O_CR  28828                  // [k1][36] = 2268
#define O_CI  31096
#define O_DR  33364                  // [m][36] = 2268
#define O_DI  35632
#define O_WCR 37900                  // [k1][36] = 2268
#define O_WCI 40168
#define O_CT  42436                  // [k][68] = 4284
#define O_ST  46720
#define O_TTC 51004                  // [n][36] = 2268
#define O_TTS 53272
#define O_W5  55540                  // 576
#define O_W1  56116                  // 160
#define O_W2  56276
#define O_KA  56436
#define SMEM_FLOATS 56452            // 225808 B

__global__ void __launch_bounds__(512) solver_kernel(const float* __restrict__ x_in,
                              const float* __restrict__ f_in,
                              const float* __restrict__ kA,
                              const float* __restrict__ w5, const float* __restrict__ b5) {
    extern __shared__ float sm[];
    float* sxp  = sm + O_SXP;
    float* srp  = sm + O_SRP;
    float* sT   = sm + O_T;
    float* sPr  = sm + O_PR;
    float* sPi  = sm + O_PI;
    float* sCr  = sm + O_CR;
    float* sCi  = sm + O_CI;
    float* sDr  = sm + O_DR;
    float* sDi  = sm + O_DI;
    float* swcr = sm + O_WCR;
    float* swci = sm + O_WCI;
    float* sct  = sm + O_CT;
    float* sst  = sm + O_ST;
    float* sttc = sm + O_TTC;
    float* stts = sm + O_TTS;
    float* sw5  = sm + O_W5;
    float* sw1  = sm + O_W1;
    float* sw2  = sm + O_W2;
    float* ska  = sm + O_KA;

    int b = blockIdx.x, tid = threadIdx.x;
    const int T = 512;
    const float inv = 0.12598815766974242f;  // 1/sqrt(63)

    // ---- init ----
    float fr[8];
    #pragma unroll
    for (int p = 0; p < 8; p++) {
        int el = tid + p*T;
        fr[p] = 0.f;
        if (el < NP64) {
            int i = el >> 6, j = el & 63;
            if (j < 63) {
                fr[p] = f_in[b*NP + i*NN + j];
                sxp[(i+1)*68 + (j+1)] = x_in[b*NP + i*NN + j];
            }
        }
    }
    for (int el = tid; el < 63*68; el += T) { sct[el] = g_cosT[el]; sst[el] = g_sinT[el]; }
    for (int el = tid; el < 63*36; el += T) { sttc[el] = g_cosTT[el]; stts[el] = g_sinTT[el]; }
    for (int c = tid; c < 65; c += T) {
        sxp[c] = (c == 64) ? 1.f : 0.f;
        sxp[64*68 + c] = 1.f;
    }
    for (int r = tid; r < 65; r += T) {
        sxp[r*68] = (r == 64) ? 1.f : 0.f;
        sxp[r*68 + 64] = 1.f;
    }
    for (int idx = tid; idx < 576; idx += T) {
        int k = idx / 64, r = idx & 63, o = r >> 5, i = r & 31;
        sw5[idx] = w5[i*18 + o*9 + k];
    }
    if (tid < 9) ska[tid] = kA[b*9 + tid];
    for (int el = tid; el < 147; el += T) {
        sw1[el] = g_w1[b*147 + el];
        sw2[el] = g_w2[b*147 + el];
    }
    __syncthreads();

    // ---- ct5 fused: h flat [2][63*63] into sT staging ----
    {
        float b0 = b5[0], b1 = b5[1];
        const float4* s_w4 = (const float4*)sw5;
        const float4* gin = (const float4*)(g_a4 + (size_t)b * 1089 * 32);
        for (int pix = tid; pix < NP; pix += T) {
            int y = pix / NN, x = pix % NN;
            float acc0 = b0, acc1 = b1;
            int kys[2], iys[2], nky, kxs[2], ixs[2], nkx;
            if (y & 1) { nky=1; kys[0]=1; iys[0]=(y+1)>>1; }
            else       { nky=2; kys[0]=0; iys[0]=(y+2)>>1; kys[1]=2; iys[1]=y>>1; }
            if (x & 1) { nkx=1; kxs[0]=1; ixs[0]=(x+1)>>1; }
            else       { nkx=2; kxs[0]=0; ixs[0]=(x+2)>>1; kxs[1]=2; ixs[1]=x>>1; }
            for (int p = 0; p < nky; p++)
                for (int q = 0; q < nkx; q++) {
                    int base4 = (iys[p]*33 + ixs[q]) * 8;
                    int kk = kys[p]*3 + kxs[q];
                    #pragma unroll
                    for (int c4 = 0; c4 < 8; c4++) {
                        float4 v = __ldg(gin + base4 + c4);
                        float4 w0 = s_w4[kk*16 + c4];
                        float4 w1 = s_w4[kk*16 + 8 + c4];
                        acc0 += v.x*w0.x + v.y*w0.y + v.z*w0.z + v.w*w0.w;
                        acc1 += v.x*w1.x + v.y*w1.y + v.z*w1.z + v.w*w1.w;
                    }
                }
            sT[pix] = acc0;
            sT[NP + pix] = acc1;
        }
    }
    __syncthreads();
    for (int el = tid; el < 2016; el += T) {
        int k1 = el >> 5, k2 = el & 31;
        int p = k1*63 + k2;
        swcr[k1*36 + k2] = sT[2*p];
        swci[k1*36 + k2] = sT[2*p + 1];
    }
    __syncthreads();
    for (int el = tid; el < 14904; el += T) sT[el] = 0.f;
    for (int el = tid; el < 4968; el += T) srp[el] = 0.f;
    __syncthreads();

    for (int iter = 0; iter < 5; iter++) {
        // ---- (a) residual -> srp ----
        #pragma unroll
        for (int p = 0; p < 8; p++) {
            int el = tid + p*T;
            if (el >= NP64) break;
            int i = el >> 6, j = el & 63;
            if (j >= 63) continue;
            const float* xb = sxp + i*68 + j;
            float acc = ska[0]*xb[0] + ska[1]*xb[1] + ska[2]*xb[2]
                      + ska[3]*xb[68] + ska[4]*xb[69] + ska[5]*xb[70]
                      + ska[6]*xb[136] + ska[7]*xb[137] + ska[8]*xb[138];
            srp[(i+3)*72 + j + 4] = fr[p] - acc;
        }
        __syncthreads();

        // ---- (b) stage1: t[c] = conv7(r, w1[c]) — 2-row blocked, 3 channels ----
        {
            int rpair = tid >> 4, g = tid & 15;
            int i0 = rpair << 1;
            bool two = (i0 + 1 < 63);
            int j0 = g << 2;
            float4 a00={0,0,0,0}, a01={0,0,0,0}, a02={0,0,0,0};
            float4 a10={0,0,0,0}, a11={0,0,0,0}, a12={0,0,0,0};
            #pragma unroll
            for (int rr_ = 0; rr_ < 8; rr_++) {
                if (rr_ == 7 && !two) break;
                const float4* rp4 = (const float4*)(srp + (i0+rr_)*72 + j0);
                float4 Ra = rp4[0], Rb = rp4[1], Rc = rp4[2];
                float rr[12] = {Ra.x,Ra.y,Ra.z,Ra.w, Rb.x,Rb.y,Rb.z,Rb.w, Rc.x,Rc.y,Rc.z,Rc.w};
                if (rr_ < 7) {
                    #pragma unroll
                    for (int v = 0; v < 7; v++) {
                        float w0 = sw1[rr_*7 + v];
                        float w1 = sw1[49 + rr_*7 + v];
                        float w2 = sw1[98 + rr_*7 + v];
                        a00.x += rr[v+1]*w0; a00.y += rr[v+2]*w0; a00.z += rr[v+3]*w0; a00.w += rr[v+4]*w0;
                        a01.x += rr[v+1]*w1; a01.y += rr[v+2]*w1; a01.z += rr[v+3]*w1; a01.w += rr[v+4]*w1;
                        a02.x += rr[v+1]*w2; a02.y += rr[v+2]*w2; a02.z += rr[v+3]*w2; a02.w += rr[v+4]*w2;
                    }
                }
                if (rr_ >= 1) {
                    int u = rr_ - 1;
                    #pragma unroll
                    for (int v = 0; v < 7; v++) {
                        float w0 = sw1[u*7 + v];
                        float w1 = sw1[49 + u*7 + v];
                        float w2 = sw1[98 + u*7 + v];
                        a10.x += rr[v+1]*w0; a10.y += rr[v+2]*w0; a10.z += rr[v+3]*w0; a10.w += rr[v+4]*w0;
                        a11.x += rr[v+1]*w1; a11.y += rr[v+2]*w1; a11.z += rr[v+3]*w1; a11.w += rr[v+4]*w1;
                        a12.x += rr[v+1]*w2; a12.y += rr[v+2]*w2; a12.z += rr[v+3]*w2; a12.w += rr[v+4]*w2;
                    }
                }
            }
            float* o0 = sT + (i0+3)*72 + j0 + 4;
            if (g < 15) {
                *(float4*)o0 = a00; *(float4*)(o0+4968) = a01; *(float4*)(o0+9936) = a02;
                if (two) {
                    float* o1 = o0 + 72;
                    *(float4*)o1 = a10; *(float4*)(o1+4968) = a11; *(float4*)(o1+9936) = a12;
                }
            } else {
                o0[0]=a00.x; o0[1]=a00.y; o0[2]=a00.z;
                o0[4968]=a01.x; o0[4969]=a01.y; o0[4970]=a01.z;
                o0[9936]=a02.x; o0[9937]=a02.y; o0[9938]=a02.z;
                if (two) {
                    float* o1 = o0 + 72;
                    o1[0]=a10.x; o1[1]=a10.y; o1[2]=a10.z;
                    o1[4968]=a11.x; o1[4969]=a11.y; o1[4970]=a11.z;
                    o1[9936]=a12.x; o1[9937]=a12.y; o1[9938]=a12.z;
                }
            }
        }
        __syncthreads();

        // ---- (c) stage2: x += sum_c conv7(t[c], w2[c]) — 2-row blocked ----
        {
            int rpair = tid >> 4, g = tid & 15;
            int i0 = rpair << 1;
            bool two = (i0 + 1 < 63);
            int j0 = g << 2;
            float4 A0 = {0,0,0,0}, A1 = {0,0,0,0};
            #pragma unroll
            for (int c = 0; c < 3; c++) {
                const float* tb = sT + c*4968;
                const float* wc_ = sw2 + c*49;
                #pragma unroll
                for (int rr_ = 0; rr_ < 8; rr_++) {
                    if (rr_ == 7 && !two) break;
                    const float4* rp4 = (const float4*)(tb + (i0+rr_)*72 + j0);
                    float4 Ra = rp4[0], Rb = rp4[1], Rc = rp4[2];
                    float rr[12] = {Ra.x,Ra.y,Ra.z,Ra.w, Rb.x,Rb.y,Rb.z,Rb.w, Rc.x,Rc.y,Rc.z,Rc.w};
                    if (rr_ < 7) {
                        #pragma unroll
                        for (int v = 0; v < 7; v++) {
                            float wv = wc_[rr_*7 + v];
                            A0.x += rr[v+1]*wv; A0.y += rr[v+2]*wv;
                            A0.z += rr[v+3]*wv; A0.w += rr[v+4]*wv;
                        }
                    }
                    if (rr_ >= 1) {
                        int u = rr_ - 1;
                        #pragma unroll
                        for (int v = 0; v < 7; v++) {
                            float wv = wc_[u*7 + v];
                            A1.x += rr[v+1]*wv; A1.y += rr[v+2]*wv;
                            A1.z += rr[v+3]*wv; A1.w += rr[v+4]*wv;
                        }
                    }
                }
            }
            float* xo0 = sxp + (i0+1)*68 + j0 + 1;
            xo0[0] += A0.x; xo0[1] += A0.y; xo0[2] += A0.z;
            if (g < 15) xo0[3] += A0.w;
            if (two) {
                float* xo1 = xo0 + 68;
                xo1[0] += A1.x; xo1[1] += A1.y; xo1[2] += A1.z;
                if (g < 15) xo1[3] += A1.w;
            }
        }
        __syncthreads();

        // ---- (d) residual -> srp ----
        #pragma unroll
        for (int p = 0; p < 8; p++) {
            int el = tid + p*T;
            if (el >= NP64) break;
            int i = el >> 6, j = el & 63;
            if (j >= 63) continue;
            const float* xb = sxp + i*68 + j;
            float acc = ska[0]*xb[0] + ska[1]*xb[1] + ska[2]*xb[2]
                      + ska[3]*xb[68] + ska[4]*xb[69] + ska[5]*xb[70]
                      + ska[6]*xb[136] + ska[7]*xb[137] + ska[8]*xb[138];
            srp[(i+3)*72 + j + 4] = fr[p] - acc;
        }
        __syncthreads();

        // ---- (P) P[m][k2] = inv * sum_n r[m,n] conj(W[k2,n]), k2<32 ----
        for (int w = tid; w < 504; w += T) {
            int m = w >> 3, q = w & 7;
            int k20 = q << 2;
            const float* rrow = srp + (m+3)*72 + 4;
            float4 ar = {0,0,0,0}, ai = {0,0,0,0};
            #pragma unroll 9
            for (int n = 0; n < 63; n++) {
                float rv = rrow[n];
                float4 c = *(const float4*)(sttc + n*36 + k20);
                float4 s = *(const float4*)(stts + n*36 + k20);
                ar.x += rv*c.x; ar.y += rv*c.y; ar.z += rv*c.z; ar.w += rv*c.w;
                ai.x -= rv*s.x; ai.y -= rv*s.y; ai.z -= rv*s.z; ai.w -= rv*s.w;
            }
            ar.x*=inv; ar.y*=inv; ar.z*=inv; ar.w*=inv;
            ai.x*=inv; ai.y*=inv; ai.z*=inv; ai.w*=inv;
            *(float4*)(sPr + m*36 + k20) = ar;
            *(float4*)(sPi + m*36 + k20) = ai;
        }
        __syncthreads();

        // ---- (C) C[k1][k2] = (inv * sum_m conj(W[k1,m]) P[m][k2]) * wc ----
        for (int w = tid; w < 504; w += T) {
            int k1 = w >> 3, q = w & 7;
            int k20 = q << 2;
            const float* crow = sct + k1*68;
            const float* srow = sst + k1*68;
            float4 ar = {0,0,0,0}, ai = {0,0,0,0};
            #pragma unroll 9
            for (int m = 0; m < 63; m++) {
                float c = crow[m], s = srow[m];
                float4 pr = *(const float4*)(sPr + m*36 + k20);
                float4 pi = *(const float4*)(sPi + m*36 + k20);
                ar.x += c*pr.x + s*pi.x;  ai.x += c*pi.x - s*pr.x;
                ar.y += c*pr.y + s*pi.y;  ai.y += c*pi.y - s*pr.y;
                ar.z += c*pr.z + s*pi.z;  ai.z += c*pi.z - s*pr.z;
                ar.w += c*pr.w + s*pi.w;  ai.w += c*pi.w - s*pr.w;
            }
            float4 wr = *(const float4*)(swcr + k1*36 + k20);
            float4 wi = *(const float4*)(swci + k1*36 + k20);
            ar.x*=inv; ar.y*=inv; ar.z*=inv; ar.w*=inv;
            ai.x*=inv; ai.y*=inv; ai.z*=inv; ai.w*=inv;
            float4 cr = {ar.x*wr.x - ai.x*wi.x, ar.y*wr.y - ai.y*wi.y,
                         ar.z*wr.z - ai.z*wi.z, ar.w*wr.w - ai.w*wi.w};
            float4 ci = {ar.x*wi.x + ai.x*wr.x, ar.y*wi.y + ai.y*wr.y,
                         ar.z*wi.z + ai.z*wr.z, ar.w*wi.w + ai.w*wr.w};
            *(float4*)(sCr + k1*36 + k20) = cr;
            *(float4*)(sCi + k1*36 + k20) = ci;
        }
        __syncthreads();

        // ---- (D) D[m][k2] = inv * sum_k1 W[m,k1] C[k1][k2] ----
        for (int w = tid; w < 504; w += T) {
            int m = w >> 3, q = w & 7;
            int k20 = q << 2;
            const float* crow = sct + m*68;
            const float* srow = sst + m*68;
            float4 dr = {0,0,0,0}, di = {0,0,0,0};
            #pragma unroll 9
            for (int k1 = 0; k1 < 63; k1++) {
                float c = crow[k1], s = srow[k1];
                float4 Cr = *(const float4*)(sCr + k1*36 + k20);
                float4 Ci = *(const float4*)(sCi + k1*36 + k20);
                dr.x += c*Cr.x - s*Ci.x;  di.x += c*Ci.x + s*Cr.x;
                dr.y += c*Cr.y - s*Ci.y;  di.y += c*Ci.y + s*Cr.y;
                dr.z += c*Cr.z - s*Ci.z;  di.z += c*Ci.z + s*Cr.z;
                dr.w += c*Cr.w - s*Ci.w;  di.w += c*Ci.w + s*Cr.w;
            }
            dr.x*=inv; dr.y*=inv; dr.z*=inv; dr.w*=inv;
            di.x*=inv; di.y*=inv; di.z*=inv; di.w*=inv;
            *(float4*)(sDr + m*36 + k20) = dr;
            *(float4*)(sDi + m*36 + k20) = di;
        }
        __syncthreads();

        // ---- (h) x[m,n] += inv*(Dr[m,0] + 2*sum_{k2=1..31} Re(D[m,k2] W[k2,n])) ----
        for (int w = tid; w < 1024; w += T) {
            int m = w >> 4, g = w & 15;
            if (m >= 63) continue;
            int n0 = g << 2;
            const float* dr_ = sDr + m*36;
            const float* di_ = sDi + m*36;
            float d0 = dr_[0];
            float ax=d0, ay=d0, az=d0, aw=d0;
            #pragma unroll 8
            for (int k2 = 1; k2 < 32; k2++) {
                float dr2 = dr_[k2]*2.f, di2 = di_[k2]*2.f;
                float4 c4 = *(const float4*)(sct + k2*68 + n0);
                float4 s4 = *(const float4*)(sst + k2*68 + n0);
                ax += dr2*c4.x - di2*s4.x;
                ay += dr2*c4.y - di2*s4.y;
                az += dr2*c4.z - di2*s4.z;
                aw += dr2*c4.w - di2*s4.w;
            }
            float* xo = sxp + (m+1)*68 + n0 + 1;
            xo[0] += ax*inv; xo[1] += ay*inv; xo[2] += az*inv;
            if (g < 15) xo[3] += aw*inv;
        }
        __syncthreads();
    }

    // ---- final residual + sum of squares ----
    float loc = 0.f;
    #pragma unroll
    for (int p = 0; p < 8; p++) {
        int el = tid + p*T;
        if (el >= NP64) break;
        int i = el >> 6, j = el & 63;
        if (j >= 63) continue;
        const float* xb = sxp + i*68 + j;
        float acc = ska[0]*xb[0] + ska[1]*xb[1] + ska[2]*xb[2]
                  + ska[3]*xb[68] + ska[4]*xb[69] + ska[5]*xb[70]
                  + ska[6]*xb[136] + ska[7]*xb[137] + ska[8]*xb[138];
        float v = fr[p] - acc;
        loc += v * v;
    }
    #pragma unroll
    for (int off = 16; off; off >>= 1)
        loc += __shfl_xor_sync(0xFFFFFFFFu, loc, off);
    __shared__ float wsum[16];
    int wid = tid >> 5;
    if ((tid & 31) == 0) wsum[wid] = loc;
    __syncthreads();
    if (tid == 0) {
        float s = 0.f;
        #pragma unroll
        for (int w = 0; w < 16; w++) s += wsum[w];
        g_blocksum[b] = s;
    }
}

__global__ void final_reduce_kernel(float* __restrict__ out) {
    __shared__ float s[BATCH];
    s[threadIdx.x] = g_blocksum[threadIdx.x];
    __syncthreads();
    for (int st = BATCH/2; st > 0; st >>= 1) {
        if (threadIdx.x < st) s[threadIdx.x] += s[threadIdx.x + st];
        __syncthreads();
    }
    if (threadIdx.x == 0) out[0] = sqrtf(s[0]) / 256.0f;
}

// ---------------- host ----------------
extern "C" void kernel_launch(void* const* d_in, const int* in_sizes, int n_in,
                              void* d_out, int out_size) {
    const float* x      = (const float*)d_in[0];
    const float* f      = (const float*)d_in[1];
    const float* kA     = (const float*)d_in[2];
    const float* fc1_w1 = (const float*)d_in[3];
    const float* fc1_b1 = (const float*)d_in[4];
    const float* fc1_w2 = (const float*)d_in[5];
    const float* fc1_b2 = (const float*)d_in[6];
    const float* fc2_w1 = (const float*)d_in[7];
    const float* fc2_b1 = (const float*)d_in[8];
    const float* fc2_w2 = (const float*)d_in[9];
    const float* fc2_b2 = (const float*)d_in[10];
    const float* ct1_w  = (const float*)d_in[11];
    const float* ct1_b  = (const float*)d_in[12];
    const float* ct2_w  = (const float*)d_in[13];
    const float* ct2_b  = (const float*)d_in[14];
    const float* ct3_w  = (const float*)d_in[15];
    const float* ct3_b  = (const float*)d_in[16];
    const float* ct4_w  = (const float*)d_in[17];
    const float* ct4_b  = (const float*)d_in[18];
    const float* ct5_w  = (const float*)d_in[19];
    const float* ct5_b  = (const float*)d_in[20];
    float* out = (float*)d_out;

    cudaFuncSetAttribute(solver_kernel, cudaFuncAttributeMaxDynamicSharedMemorySize,
                         SMEM_FLOATS * (int)sizeof(float));
    cudaFuncSetAttribute(ctchain_kernel, cudaFuncAttributeMaxDynamicSharedMemorySize,
                         21248 * (int)sizeof(float));

    hyper_kernel<<<BATCH, 256>>>(kA, fc1_w1, fc1_b1, fc1_w2, fc1_b2,
                                 fc2_w1, fc2_b1, fc2_w2, fc2_b2);
    ctchain_kernel<<<BATCH, 512, 21248 * sizeof(float)>>>(kA, ct1_w, ct1_b, ct2_w, ct2_b,
                                                          ct3_w, ct3_b, ct4_w, ct4_b);
    init_tw_kernel<<<(63*68 + 255)/256, 256>>>();
    solver_kernel<<<BATCH, 512, SMEM_FLOATS * sizeof(float)>>>(x, f, kA, ct5_w, ct5_b);
    final_reduce_kernel<<<1, BATCH>>>(out);
}

// round 8
// speedup vs baseline: 3.6400x; 1.1030x over previous
#include <cuda_runtime.h>
#include <math.h>

#define NN 63
#define NP (NN*NN)          // 3969
#define NP64 4032
#define BATCH 256
#define KS 7
#define ML 3

// ---------------- device scratch ----------------
__device__ float g_cosT[63*68];   // [k][n] rows padded to 68, cols 63..67 = 0
__device__ float g_sinT[63*68];
__device__ float g_cosTT[63*36];  // transposed [n][k2<32], stride 36
__device__ float g_sinTT[63*36];
__device__ float g_w1[BATCH*147];
__device__ float g_w2[BATCH*147];
__device__ float g_a4[BATCH*1089*32];   // [b][pix][ch]
__device__ float g_blocksum[BATCH];

__device__ __forceinline__ float gelu_exact(float v) {
    return v * 0.5f * (1.0f + erff(v * 0.70710678118654752f));
}

__global__ void init_tw_kernel() {
    int idx = blockIdx.x * blockDim.x + threadIdx.x;
    if (idx < 63*68) {
        int k = idx / 68, n = idx % 68;
        if (n < 63) {
            float ang = 6.28318530717958647692f * (float)((k * n) % NN) / 63.0f;
            g_cosT[idx] = cosf(ang);
            g_sinT[idx] = sinf(ang);
        } else { g_cosT[idx] = 0.f; g_sinT[idx] = 0.f; }
    }
    if (idx < 63*36) {
        int n = idx / 36, k2 = idx % 36;
        if (k2 < 32) {
            float ang = 6.28318530717958647692f * (float)((k2 * n) % NN) / 63.0f;
            g_cosTT[idx] = cosf(ang);
            g_sinTT[idx] = sinf(ang);
        } else { g_cosTT[idx] = 0.f; g_sinTT[idx] = 0.f; }
    }
}

// ---------------- hypernet ----------------
__global__ void hyper_kernel(const float* __restrict__ kA,
                             const float* __restrict__ w1a, const float* __restrict__ b1a,
                             const float* __restrict__ w2a, const float* __restrict__ b2a,
                             const float* __restrict__ w1b, const float* __restrict__ b1b,
                             const float* __restrict__ w2b, const float* __restrict__ b2b) {
    int b = blockIdx.x;
    __shared__ float a[9], h1[100], h2[100];
    int t = threadIdx.x;
    if (t < 9) a[t] = kA[b*9 + t];
    __syncthreads();
    if (t < 100) {
        float s = b1a[t];
        #pragma unroll
        for (int i = 0; i < 9; i++) s += a[i] * w1a[i*100 + t];
        h1[t] = gelu_exact(s);
    } else if (t < 200) {
        int h = t - 100;
        float s = b1b[h];
        #pragma unroll
        for (int i = 0; i < 9; i++) s += a[i] * w1b[i*100 + h];
        h2[h] = gelu_exact(s);
    }
    __syncthreads();
    for (int o = t; o < 147; o += blockDim.x) {
        float s1 = b2a[o], s2 = b2b[o];
        for (int h = 0; h < 100; h++) {
            s1 += h1[h] * w2a[h*147 + o];
            s2 += h2[h] * w2b[h*147 + o];
        }
        g_w1[b*147 + o] = s1;
        g_w2[b*147 + o] = s2;
    }
}

// ---------------- fused ConvTranspose chain ct1..ct4 ----------------
__device__ __forceinline__ void load_ctw(const float* __restrict__ w,
                                         const float* __restrict__ bias,
                                         float* s_w, float* s_bias, int tid) {
    for (int idx = tid; idx < 9216; idx += 512) {
        int i = idx & 31, o = (idx >> 5) & 31, k = idx >> 10;
        s_w[k*1040 + (o>>3)*260 + (o&7)*32 + i] = w[(i*32 + o)*9 + k];
    }
    if (tid < 32) s_bias[tid] = bias[tid];
}

template<int IN_H>
__device__ void ct_midstage(const float* __restrict__ s_in, const float* __restrict__ s_w,
                            const float* __restrict__ s_bias, float* __restrict__ out, int tid) {
    constexpr int OUT_H = 2*IN_H - 1;
    constexpr int OUT_SZ = OUT_H*OUT_H;
    const float4* in4 = (const float4*)s_in;
    const float4* w4  = (const float4*)s_w;
    for (int it = tid; it < OUT_SZ*4; it += 512) {
        int pix = it >> 2, og = it & 3;
        int y = pix / OUT_H, x = pix % OUT_H;
        float acc[8];
        #pragma unroll
        for (int ol = 0; ol < 8; ol++) acc[ol] = s_bias[og*8 + ol];
        int kys[2], iys[2], nky, kxs[2], ixs[2], nkx;
        if (y & 1) { nky=2; kys[0]=0; iys[0]=(y+1)>>1; kys[1]=2; iys[1]=(y-1)>>1; }
        else       { nky=1; kys[0]=1; iys[0]=y>>1; }
        if (x & 1) { nkx=2; kxs[0]=0; ixs[0]=(x+1)>>1; kxs[1]=2; ixs[1]=(x-1)>>1; }
        else       { nkx=1; kxs[0]=1; ixs[0]=x>>1; }
        for (int p = 0; p < nky; p++)
            for (int q = 0; q < nkx; q++) {
                int base4 = (iys[p]*IN_H + ixs[q]) * 8;
                const float4* wrow = w4 + (kys[p]*3 + kxs[q])*260 + og*65;
                #pragma unroll
                for (int c4 = 0; c4 < 8; c4++) {
                    float4 v = in4[base4 + c4];
                    #pragma unroll
                    for (int ol = 0; ol < 8; ol++) {
                        float4 wv = wrow[ol*8 + c4];
                        acc[ol] += v.x*wv.x + v.y*wv.y + v.z*wv.z + v.w*wv.w;
                    }
                }
            }
        float* ob = out + pix*32 + og*8;
        float4 o0 = {gelu_exact(acc[0]), gelu_exact(acc[1]), gelu_exact(acc[2]), gelu_exact(acc[3])};
        float4 o1 = {gelu_exact(acc[4]), gelu_exact(acc[5]), gelu_exact(acc[6]), gelu_exact(acc[7])};
        *(float4*)ob = o0;
        *(float4*)(ob + 4) = o1;
    }
}

__global__ void __launch_bounds__(512) ctchain_kernel(
    const float* __restrict__ kA,
    const float* __restrict__ w1c, const float* __restrict__ b1c,
    const float* __restrict__ w2c, const float* __restrict__ b2c,
    const float* __restrict__ w3c, const float* __restrict__ b3c,
    const float* __restrict__ w4c, const float* __restrict__ b4c) {
    extern __shared__ float cs[];
    float* s_w    = cs;               // 9360
    float* B1     = cs + 9360;        // 9248
    float* B2     = B1 + 9248;        // 2592
    float* s_a    = B2 + 2592;        // 16
    float* s_bias = s_a + 16;         // 32
    int b = blockIdx.x, tid = threadIdx.x;

    if (tid < 9) s_a[tid] = kA[b*9 + tid];
    load_ctw(w2c, b2c, s_w, s_bias, tid);
    __syncthreads();

    for (int el = tid; el < 800; el += 512) {
        int pix = el >> 5, o = el & 31;
        int y = pix / 5, x = pix % 5;
        float acc = b1c[o];
        int kys[2], iys[2], nky, kxs[2], ixs[2], nkx;
        if (y & 1) { nky=2; kys[0]=0; iys[0]=(y+1)>>1; kys[1]=2; iys[1]=(y-1)>>1; }
        else       { nky=1; kys[0]=1; iys[0]=y>>1; }
        if (x & 1) { nkx=2; kxs[0]=0; ixs[0]=(x+1)>>1; kxs[1]=2; ixs[1]=(x-1)>>1; }
        else       { nkx=1; kxs[0]=1; ixs[0]=x>>1; }
        for (int p = 0; p < nky; p++)
            for (int q = 0; q < nkx; q++)
                acc += s_a[iys[p]*3 + ixs[q]] * w1c[o*9 + kys[p]*3 + kxs[q]];
        B1[pix*32 + o] = gelu_exact(acc);
    }
    __syncthreads();

    ct_midstage<5>(B1, s_w, s_bias, B2, tid);
    __syncthreads();
    load_ctw(w3c, b3c, s_w, s_bias, tid);
    __syncthreads();
    ct_midstage<9>(B2, s_w, s_bias, B1, tid);
    __syncthreads();
    load_ctw(w4c, b4c, s_w, s_bias, tid);
    __syncthreads();
    ct_midstage<17>(B1, s_w, s_bias, g_a4 + (size_t)b*1089*32, tid);
}

// ---------------- persistent per-sample solver ----------------
#define O_SXP 0                      // 65x68 = 4420
#define O_SRP 4420                   // 69x72 = 4968
#define O_T   9388                   // 3*4968 = 14904 (ct5 staging 7938 fits)
#define O_PR  24292                  // [m][36] = 2268
#define O_PI  26560
#define O_CR  28828                  // [k1][36] = 2268
#define O_CI  31096
#define O_DR  33364                  // [m][36] = 2268
#define O_DI  35632
#define O_WCR 37900                  // [k1][36] = 2268
#define O_WCI 40168
#define O_CT  42436                  // [k][68] = 4284
#define O_ST  46720
#define O_TTC 51004                  // [n][36] = 2268
#define O_TTS 53272
#define O_W5  55540                  // 576
#define O_W1  56116                  // 160
#define O_W2  56276
#define O_KA  56436
#define SMEM_FLOATS 56452            // 225808 B

__global__ void __launch_bounds__(512) solver_kernel(const float* __restrict__ x_in,
                              const float* __restrict__ f_in,
                              const float* __restrict__ kA,
                              const float* __restrict__ w5, const float* __restrict__ b5) {
    extern __shared__ float sm[];
    float* sxp  = sm + O_SXP;
    float* srp  = sm + O_SRP;
    float* sT   = sm + O_T;
    float* sPr  = sm + O_PR;
    float* sPi  = sm + O_PI;
    float* sCr  = sm + O_CR;
    float* sCi  = sm + O_CI;
    float* sDr  = sm + O_DR;
    float* sDi  = sm + O_DI;
    float* swcr = sm + O_WCR;
    float* swci = sm + O_WCI;
    float* sct  = sm + O_CT;
    float* sst  = sm + O_ST;
    float* sttc = sm + O_TTC;
    float* stts = sm + O_TTS;
    float* sw5  = sm + O_W5;
    float* sw1  = sm + O_W1;
    float* sw2  = sm + O_W2;
    float* ska  = sm + O_KA;

    int b = blockIdx.x, tid = threadIdx.x;
    const int T = 512;
    const float inv = 0.12598815766974242f;  // 1/sqrt(63)

    // ---- init ----
    float fr[8];
    #pragma unroll
    for (int p = 0; p < 8; p++) {
        int el = tid + p*T;
        fr[p] = 0.f;
        if (el < NP64) {
            int i = el >> 6, j = el & 63;
            if (j < 63) {
                fr[p] = f_in[b*NP + i*NN + j];
                sxp[(i+1)*68 + (j+1)] = x_in[b*NP + i*NN + j];
            }
        }
    }
    for (int el = tid; el < 63*68; el += T) { sct[el] = g_cosT[el]; sst[el] = g_sinT[el]; }
    for (int el = tid; el < 63*36; el += T) { sttc[el] = g_cosTT[el]; stts[el] = g_sinTT[el]; }
    for (int c = tid; c < 65; c += T) {
        sxp[c] = (c == 64) ? 1.f : 0.f;
        sxp[64*68 + c] = 1.f;
    }
    for (int r = tid; r < 65; r += T) {
        sxp[r*68] = (r == 64) ? 1.f : 0.f;
        sxp[r*68 + 64] = 1.f;
    }
    for (int idx = tid; idx < 576; idx += T) {
        int k = idx / 64, r = idx & 63, o = r >> 5, i = r & 31;
        sw5[idx] = w5[i*18 + o*9 + k];
    }
    if (tid < 9) ska[tid] = kA[b*9 + tid];
    for (int el = tid; el < 147; el += T) {
        sw1[el] = g_w1[b*147 + el];
        sw2[el] = g_w2[b*147 + el];
    }
    __syncthreads();

    // ---- ct5 fused: h flat [2][63*63] into sT staging ----
    {
        float b0 = b5[0], b1 = b5[1];
        const float4* s_w4 = (const float4*)sw5;
        const float4* gin = (const float4*)(g_a4 + (size_t)b * 1089 * 32);
        for (int pix = tid; pix < NP; pix += T) {
            int y = pix / NN, x = pix % NN;
            float acc0 = b0, acc1 = b1;
            int kys[2], iys[2], nky, kxs[2], ixs[2], nkx;
            if (y & 1) { nky=1; kys[0]=1; iys[0]=(y+1)>>1; }
            else       { nky=2; kys[0]=0; iys[0]=(y+2)>>1; kys[1]=2; iys[1]=y>>1; }
            if (x & 1) { nkx=1; kxs[0]=1; ixs[0]=(x+1)>>1; }
            else       { nkx=2; kxs[0]=0; ixs[0]=(x+2)>>1; kxs[1]=2; ixs[1]=x>>1; }
            for (int p = 0; p < nky; p++)
                for (int q = 0; q < nkx; q++) {
                    int base4 = (iys[p]*33 + ixs[q]) * 8;
                    int kk = kys[p]*3 + kxs[q];
                    #pragma unroll
                    for (int c4 = 0; c4 < 8; c4++) {
                        float4 v = __ldg(gin + base4 + c4);
                        float4 w0 = s_w4[kk*16 + c4];
                        float4 w1 = s_w4[kk*16 + 8 + c4];
                        acc0 += v.x*w0.x + v.y*w0.y + v.z*w0.z + v.w*w0.w;
                        acc1 += v.x*w1.x + v.y*w1.y + v.z*w1.z + v.w*w1.w;
                    }
                }
            sT[pix] = acc0;
            sT[NP + pix] = acc1;
        }
    }
    __syncthreads();
    for (int el = tid; el < 2016; el += T) {
        int k1 = el >> 5, k2 = el & 31;
        int p = k1*63 + k2;
        swcr[k1*36 + k2] = sT[2*p];
        swci[k1*36 + k2] = sT[2*p + 1];
    }
    __syncthreads();
    for (int el = tid; el < 14904; el += T) sT[el] = 0.f;
    for (int el = tid; el < 4968; el += T) srp[el] = 0.f;
    __syncthreads();

    for (int iter = 0; iter < 5; iter++) {
        // ---- (a) residual -> srp ----
        #pragma unroll
        for (int p = 0; p < 8; p++) {
            int el = tid + p*T;
            if (el >= NP64) break;
            int i = el >> 6, j = el & 63;
            if (j >= 63) continue;
            const float* xb = sxp + i*68 + j;
            float acc = ska[0]*xb[0] + ska[1]*xb[1] + ska[2]*xb[2]
                      + ska[3]*xb[68] + ska[4]*xb[69] + ska[5]*xb[70]
                      + ska[6]*xb[136] + ska[7]*xb[137] + ska[8]*xb[138];
            srp[(i+3)*72 + j + 4] = fr[p] - acc;
        }
        __syncthreads();

        // ---- (b) stage1: t[c] = conv7(r, w1[c]) — 2-row blocked, 3 channels ----
        {
            int rpair = tid >> 4, g = tid & 15;
            int i0 = rpair << 1;
            bool two = (i0 + 1 < 63);
            int j0 = g << 2;
            float4 a00={0,0,0,0}, a01={0,0,0,0}, a02={0,0,0,0};
            float4 a10={0,0,0,0}, a11={0,0,0,0}, a12={0,0,0,0};
            #pragma unroll
            for (int rr_ = 0; rr_ < 8; rr_++) {
                if (rr_ == 7 && !two) break;
                const float4* rp4 = (const float4*)(srp + (i0+rr_)*72 + j0);
                float4 Ra = rp4[0], Rb = rp4[1], Rc = rp4[2];
                float rr[12] = {Ra.x,Ra.y,Ra.z,Ra.w, Rb.x,Rb.y,Rb.z,Rb.w, Rc.x,Rc.y,Rc.z,Rc.w};
                if (rr_ < 7) {
                    #pragma unroll
                    for (int v = 0; v < 7; v++) {
                        float w0 = sw1[rr_*7 + v];
                        float w1 = sw1[49 + rr_*7 + v];
                        float w2 = sw1[98 + rr_*7 + v];
                        a00.x += rr[v+1]*w0; a00.y += rr[v+2]*w0; a00.z += rr[v+3]*w0; a00.w += rr[v+4]*w0;
                        a01.x += rr[v+1]*w1; a01.y += rr[v+2]*w1; a01.z += rr[v+3]*w1; a01.w += rr[v+4]*w1;
                        a02.x += rr[v+1]*w2; a02.y += rr[v+2]*w2; a02.z += rr[v+3]*w2; a02.w += rr[v+4]*w2;
                    }
                }
                if (rr_ >= 1) {
                    int u = rr_ - 1;
                    #pragma unroll
                    for (int v = 0; v < 7; v++) {
                        float w0 = sw1[u*7 + v];
                        float w1 = sw1[49 + u*7 + v];
                        float w2 = sw1[98 + u*7 + v];
                        a10.x += rr[v+1]*w0; a10.y += rr[v+2]*w0; a10.z += rr[v+3]*w0; a10.w += rr[v+4]*w0;
                        a11.x += rr[v+1]*w1; a11.y += rr[v+2]*w1; a11.z += rr[v+3]*w1; a11.w += rr[v+4]*w1;
                        a12.x += rr[v+1]*w2; a12.y += rr[v+2]*w2; a12.z += rr[v+3]*w2; a12.w += rr[v+4]*w2;
                    }
                }
            }
            float* o0 = sT + (i0+3)*72 + j0 + 4;
            if (g < 15) {
                *(float4*)o0 = a00; *(float4*)(o0+4968) = a01; *(float4*)(o0+9936) = a02;
                if (two) {
                    float* o1 = o0 + 72;
                    *(float4*)o1 = a10; *(float4*)(o1+4968) = a11; *(float4*)(o1+9936) = a12;
                }
            } else {
                o0[0]=a00.x; o0[1]=a00.y; o0[2]=a00.z;
                o0[4968]=a01.x; o0[4969]=a01.y; o0[4970]=a01.z;
                o0[9936]=a02.x; o0[9937]=a02.y; o0[9938]=a02.z;
                if (two) {
                    float* o1 = o0 + 72;
                    o1[0]=a10.x; o1[1]=a10.y; o1[2]=a10.z;
                    o1[4968]=a11.x; o1[4969]=a11.y; o1[4970]=a11.z;
                    o1[9936]=a12.x; o1[9937]=a12.y; o1[9938]=a12.z;
                }
            }
        }
        __syncthreads();

        // ---- (c) stage2: x += sum_c conv7(t[c], w2[c]) — 2-row x 8-wide ----
        if (tid < 256) {
            int rp = tid >> 3, g = tid & 7;
            int i0 = rp << 1;
            bool two = (i0 + 1 < 63);
            int j0 = g << 3;
            float4 A0a={0,0,0,0}, A0b={0,0,0,0}, A1a={0,0,0,0}, A1b={0,0,0,0};
            #pragma unroll
            for (int c = 0; c < 3; c++) {
                const float* tb = sT + c*4968;
                const float* wc_ = sw2 + c*49;
                #pragma unroll
                for (int rr_ = 0; rr_ < 8; rr_++) {
                    if (rr_ == 7 && !two) break;
                    const float4* rp4 = (const float4*)(tb + (i0+rr_)*72 + j0);
                    float4 Ra = rp4[0], Rb = rp4[1], Rc = rp4[2], Rd = rp4[3];
                    float rr[16] = {Ra.x,Ra.y,Ra.z,Ra.w, Rb.x,Rb.y,Rb.z,Rb.w,
                                    Rc.x,Rc.y,Rc.z,Rc.w, Rd.x,Rd.y,Rd.z,Rd.w};
                    if (rr_ < 7) {
                        #pragma unroll
                        for (int v = 0; v < 7; v++) {
                            float wv = wc_[rr_*7 + v];
                            A0a.x += rr[v+1]*wv; A0a.y += rr[v+2]*wv;
                            A0a.z += rr[v+3]*wv; A0a.w += rr[v+4]*wv;
                            A0b.x += rr[v+5]*wv; A0b.y += rr[v+6]*wv;
                            A0b.z += rr[v+7]*wv; A0b.w += rr[v+8]*wv;
                        }
                    }
                    if (rr_ >= 1) {
                        int u = rr_ - 1;
                        #pragma unroll
                        for (int v = 0; v < 7; v++) {
                            float wv = wc_[u*7 + v];
                            A1a.x += rr[v+1]*wv; A1a.y += rr[v+2]*wv;
                            A1a.z += rr[v+3]*wv; A1a.w += rr[v+4]*wv;
                            A1b.x += rr[v+5]*wv; A1b.y += rr[v+6]*wv;
                            A1b.z += rr[v+7]*wv; A1b.w += rr[v+8]*wv;
                        }
                    }
                }
            }
            float* xo0 = sxp + (i0+1)*68 + j0 + 1;
            xo0[0]+=A0a.x; xo0[1]+=A0a.y; xo0[2]+=A0a.z; xo0[3]+=A0a.w;
            xo0[4]+=A0b.x; xo0[5]+=A0b.y; xo0[6]+=A0b.z;
            if (g < 7) xo0[7]+=A0b.w;
            if (two) {
                float* xo1 = xo0 + 68;
                xo1[0]+=A1a.x; xo1[1]+=A1a.y; xo1[2]+=A1a.z; xo1[3]+=A1a.w;
                xo1[4]+=A1b.x; xo1[5]+=A1b.y; xo1[6]+=A1b.z;
                if (g < 7) xo1[7]+=A1b.w;
            }
        }
        __syncthreads();

        // ---- (d) residual -> srp ----
        #pragma unroll
        for (int p = 0; p < 8; p++) {
            int el = tid + p*T;
            if (el >= NP64) break;
            int i = el >> 6, j = el & 63;
            if (j >= 63) continue;
            const float* xb = sxp + i*68 + j;
            float acc = ska[0]*xb[0] + ska[1]*xb[1] + ska[2]*xb[2]
                      + ska[3]*xb[68] + ska[4]*xb[69] + ska[5]*xb[70]
                      + ska[6]*xb[136] + ska[7]*xb[137] + ska[8]*xb[138];
            srp[(i+3)*72 + j + 4] = fr[p] - acc;
        }
        __syncthreads();

        // ---- (P) P[m][k2] = inv * sum_n r[m,n] conj(W[k2,n]) — 2m x 4k2 ----
        if (tid < 256) {
            int mp = tid >> 3, q = tid & 7;
            int m0 = mp << 1, m1 = m0 + 1;     // m1 may be 63 (halo zeros)
            int k20 = q << 2;
            const float* r0p = srp + (m0+3)*72 + 4;
            const float* r1p = r0p + 72;
            float4 ar0={0,0,0,0}, ai0={0,0,0,0}, ar1={0,0,0,0}, ai1={0,0,0,0};
            #pragma unroll 7
            for (int n = 0; n < 63; n++) {
                float rv0 = r0p[n], rv1 = r1p[n];
                float4 c = *(const float4*)(sttc + n*36 + k20);
                float4 s = *(const float4*)(stts + n*36 + k20);
                ar0.x += rv0*c.x; ar0.y += rv0*c.y; ar0.z += rv0*c.z; ar0.w += rv0*c.w;
                ai0.x -= rv0*s.x; ai0.y -= rv0*s.y; ai0.z -= rv0*s.z; ai0.w -= rv0*s.w;
                ar1.x += rv1*c.x; ar1.y += rv1*c.y; ar1.z += rv1*c.z; ar1.w += rv1*c.w;
                ai1.x -= rv1*s.x; ai1.y -= rv1*s.y; ai1.z -= rv1*s.z; ai1.w -= rv1*s.w;
            }
            float4 R0 = {ar0.x*inv, ar0.y*inv, ar0.z*inv, ar0.w*inv};
            float4 I0 = {ai0.x*inv, ai0.y*inv, ai0.z*inv, ai0.w*inv};
            *(float4*)(sPr + m0*36 + k20) = R0;
            *(float4*)(sPi + m0*36 + k20) = I0;
            if (m1 < 63) {
                float4 R1 = {ar1.x*inv, ar1.y*inv, ar1.z*inv, ar1.w*inv};
                float4 I1 = {ai1.x*inv, ai1.y*inv, ai1.z*inv, ai1.w*inv};
                *(float4*)(sPr + m1*36 + k20) = R1;
                *(float4*)(sPi + m1*36 + k20) = I1;
            }
        }
        __syncthreads();

        // ---- (C) C[k1][k2] = (inv * sum_m conj(W[k1,m]) P[m][k2]) * wc — 2k1 x 4k2 ----
        if (tid < 256) {
            int kp = tid >> 3, q = tid & 7;
            int k10 = kp << 1, k11 = k10 + 1;
            int k11c = (k11 < 63) ? k11 : 62;
            int k20 = q << 2;
            const float* c0 = sct + k10*68;
            const float* s0 = sst + k10*68;
            const float* c1 = sct + k11c*68;
            const float* s1p = sst + k11c*68;
            float4 ar0={0,0,0,0}, ai0={0,0,0,0}, ar1={0,0,0,0}, ai1={0,0,0,0};
            #pragma unroll 7
            for (int m = 0; m < 63; m++) {
                float cw0 = c0[m], sw0 = s0[m];
                float cw1 = c1[m], sw1v = s1p[m];
                float4 pr = *(const float4*)(sPr + m*36 + k20);
                float4 pi = *(const float4*)(sPi + m*36 + k20);
                ar0.x += cw0*pr.x + sw0*pi.x;  ai0.x += cw0*pi.x - sw0*pr.x;
                ar0.y += cw0*pr.y + sw0*pi.y;  ai0.y += cw0*pi.y - sw0*pr.y;
                ar0.z += cw0*pr.z + sw0*pi.z;  ai0.z += cw0*pi.z - sw0*pr.z;
                ar0.w += cw0*pr.w + sw0*pi.w;  ai0.w += cw0*pi.w - sw0*pr.w;
                ar1.x += cw1*pr.x + sw1v*pi.x;  ai1.x += cw1*pi.x - sw1v*pr.x;
                ar1.y += cw1*pr.y + sw1v*pi.y;  ai1.y += cw1*pi.y - sw1v*pr.y;
                ar1.z += cw1*pr.z + sw1v*pi.z;  ai1.z += cw1*pi.z - sw1v*pr.z;
                ar1.w += cw1*pr.w + sw1v*pi.w;  ai1.w += cw1*pi.w - sw1v*pr.w;
            }
            {
                float4 wr = *(const float4*)(swcr + k10*36 + k20);
                float4 wi = *(const float4*)(swci + k10*36 + k20);
                float4 arv = {ar0.x*inv, ar0.y*inv, ar0.z*inv, ar0.w*inv};
                float4 aiv = {ai0.x*inv, ai0.y*inv, ai0.z*inv, ai0.w*inv};
                float4 cr = {arv.x*wr.x - aiv.x*wi.x, arv.y*wr.y - aiv.y*wi.y,
                             arv.z*wr.z - aiv.z*wi.z, arv.w*wr.w - aiv.w*wi.w};
                float4 ci = {arv.x*wi.x + aiv.x*wr.x, arv.y*wi.y + aiv.y*wr.y,
                             arv.z*wi.z + aiv.z*wr.z, arv.w*wi.w + aiv.w*wr.w};
                *(float4*)(sCr + k10*36 + k20) = cr;
                *(float4*)(sCi + k10*36 + k20) = ci;
            }
            if (k11 < 63) {
                float4 wr = *(const float4*)(swcr + k11*36 + k20);
                float4 wi = *(const float4*)(swci + k11*36 + k20);
                float4 arv = {ar1.x*inv, ar1.y*inv, ar1.z*inv, ar1.w*inv};
                float4 aiv = {ai1.x*inv, ai1.y*inv, ai1.z*inv, ai1.w*inv};
                float4 cr = {arv.x*wr.x - aiv.x*wi.x, arv.y*wr.y - aiv.y*wi.y,
                             arv.z*wr.z - aiv.z*wi.z, arv.w*wr.w - aiv.w*wi.w};
                float4 ci = {arv.x*wi.x + aiv.x*wr.x, arv.y*wi.y + aiv.y*wr.y,
                             arv.z*wi.z + aiv.z*wr.z, arv.w*wi.w + aiv.w*wr.w};
                *(float4*)(sCr + k11*36 + k20) = cr;
                *(float4*)(sCi + k11*36 + k20) = ci;
            }
        }
        __syncthreads();

        // ---- (D) D[m][k2] = inv * sum_k1 W[m,k1] C[k1][k2] — 2m x 4k2 ----
        if (tid < 256) {
            int mp = tid >> 3, q = tid & 7;
            int m0 = mp << 1, m1 = m0 + 1;
            int m1c = (m1 < 63) ? m1 : 62;
            int k20 = q << 2;
            const float* c0 = sct + m0*68;
            const float* s0 = sst + m0*68;
            const float* c1 = sct + m1c*68;
            const float* s1p = sst + m1c*68;
            float4 dr0={0,0,0,0}, di0={0,0,0,0}, dr1={0,0,0,0}, di1={0,0,0,0};
            #pragma unroll 7
            for (int k1 = 0; k1 < 63; k1++) {
                float cw0 = c0[k1], sw0 = s0[k1];
                float cw1 = c1[k1], sw1v = s1p[k1];
                float4 Cr = *(const float4*)(sCr + k1*36 + k20);
                float4 Ci = *(const float4*)(sCi + k1*36 + k20);
                dr0.x += cw0*Cr.x - sw0*Ci.x;  di0.x += cw0*Ci.x + sw0*Cr.x;
                dr0.y += cw0*Cr.y - sw0*Ci.y;  di0.y += cw0*Ci.y + sw0*Cr.y;
                dr0.z += cw0*Cr.z - sw0*Ci.z;  di0.z += cw0*Ci.z + sw0*Cr.z;
                dr0.w += cw0*Cr.w - sw0*Ci.w;  di0.w += cw0*Ci.w + sw0*Cr.w;
                dr1.x += cw1*Cr.x - sw1v*Ci.x;  di1.x += cw1*Ci.x + sw1v*Cr.x;
                dr1.y += cw1*Cr.y - sw1v*Ci.y;  di1.y += cw1*Ci.y + sw1v*Cr.y;
                dr1.z += cw1*Cr.z - sw1v*Ci.z;  di1.z += cw1*Ci.z + sw1v*Cr.z;
                dr1.w += cw1*Cr.w - sw1v*Ci.w;  di1.w += cw1*Ci.w + sw1v*Cr.w;
            }
            float4 R0 = {dr0.x*inv, dr0.y*inv, dr0.z*inv, dr0.w*inv};
            float4 I0 = {di0.x*inv, di0.y*inv, di0.z*inv, di0.w*inv};
            *(float4*)(sDr + m0*36 + k20) = R0;
            *(float4*)(sDi + m0*36 + k20) = I0;
            if (m1 < 63) {
                float4 R1 = {dr1.x*inv, dr1.y*inv, dr1.z*inv, dr1.w*inv};
                float4 I1 = {di1.x*inv, di1.y*inv, di1.z*inv, di1.w*inv};
                *(float4*)(sDr + m1*36 + k20) = R1;
                *(float4*)(sDi + m1*36 + k20) = I1;
            }
        }
        __syncthreads();

        // ---- (h) x[m,n] += inv*(Dr[m,0] + 2*sum Re(D[m,k2] W[k2,n])) — 2m x 4n ----
        {
            int mp = tid >> 4, g = tid & 15;
            int m0 = mp << 1, m1 = m0 + 1;
            bool two = (m1 < 63);
            int n0 = g << 2;
            const float* d0r = sDr + m0*36;
            const float* d0i = sDi + m0*36;
            const float* d1r = sDr + m1*36;   // m1==63 reads into sDi region: harmless, discarded
            const float* d1i = sDi + m1*36;
            float4 A0 = {0,0,0,0}, A1 = {0,0,0,0};
            float b0v = d0r[0], b1v = d1r[0];
            #pragma unroll 8
            for (int k2 = 1; k2 < 32; k2++) {
                float4 c4 = *(const float4*)(sct + k2*68 + n0);
                float4 s4 = *(const float4*)(sst + k2*68 + n0);
                float e0r = d0r[k2]*2.f, e0i = d0i[k2]*2.f;
                float e1r = d1r[k2]*2.f, e1i = d1i[k2]*2.f;
                A0.x += e0r*c4.x - e0i*s4.x;
                A0.y += e0r*c4.y - e0i*s4.y;
                A0.z += e0r*c4.z - e0i*s4.z;
                A0.w += e0r*c4.w - e0i*s4.w;
                A1.x += e1r*c4.x - e1i*s4.x;
                A1.y += e1r*c4.y - e1i*s4.y;
                A1.z += e1r*c4.z - e1i*s4.z;
                A1.w += e1r*c4.w - e1i*s4.w;
            }
            float* xo0 = sxp + (m0+1)*68 + n0 + 1;
            xo0[0] += (b0v + A0.x)*inv;
            xo0[1] += (b0v + A0.y)*inv;
            xo0[2] += (b0v + A0.z)*inv;
            if (g < 15) xo0[3] += (b0v + A0.w)*inv;
            if (two) {
                float* xo1 = sxp + (m1+1)*68 + n0 + 1;
                xo1[0] += (b1v + A1.x)*inv;
                xo1[1] += (b1v + A1.y)*inv;
                xo1[2] += (b1v + A1.z)*inv;
                if (g < 15) xo1[3] += (b1v + A1.w)*inv;
            }
        }
        __syncthreads();
    }

    // ---- final residual + sum of squares ----
    float loc = 0.f;
    #pragma unroll
    for (int p = 0; p < 8; p++) {
        int el = tid + p*T;
        if (el >= NP64) break;
        int i = el >> 6, j = el & 63;
        if (j >= 63) continue;
        const float* xb = sxp + i*68 + j;
        float acc = ska[0]*xb[0] + ska[1]*xb[1] + ska[2]*xb[2]
                  + ska[3]*xb[68] + ska[4]*xb[69] + ska[5]*xb[70]
                  + ska[6]*xb[136] + ska[7]*xb[137] + ska[8]*xb[138];
        float v = fr[p] - acc;
        loc += v * v;
    }
    #pragma unroll
    for (int off = 16; off; off >>= 1)
        loc += __shfl_xor_sync(0xFFFFFFFFu, loc, off);
    __shared__ float wsum[16];
    int wid = tid >> 5;
    if ((tid & 31) == 0) wsum[wid] = loc;
    __syncthreads();
    if (tid == 0) {
        float s = 0.f;
        #pragma unroll
        for (int w = 0; w < 16; w++) s += wsum[w];
        g_blocksum[b] = s;
    }
}

__global__ void final_reduce_kernel(float* __restrict__ out) {
    __shared__ float s[BATCH];
    s[threadIdx.x] = g_blocksum[threadIdx.x];
    __syncthreads();
    for (int st = BATCH/2; st > 0; st >>= 1) {
        if (threadIdx.x < st) s[threadIdx.x] += s[threadIdx.x + st];
        __syncthreads();
    }
    if (threadIdx.x == 0) out[0] = sqrtf(s[0]) / 256.0f;
}

// ---------------- host ----------------
extern "C" void kernel_launch(void* const* d_in, const int* in_sizes, int n_in,
                              void* d_out, int out_size) {
    const float* x      = (const float*)d_in[0];
    const float* f      = (const float*)d_in[1];
    const float* kA     = (const float*)d_in[2];
    const float* fc1_w1 = (const float*)d_in[3];
    const float* fc1_b1 = (const float*)d_in[4];
    const float* fc1_w2 = (const float*)d_in[5];
    const float* fc1_b2 = (const float*)d_in[6];
    const float* fc2_w1 = (const float*)d_in[7];
    const float* fc2_b1 = (const float*)d_in[8];
    const float* fc2_w2 = (const float*)d_in[9];
    const float* fc2_b2 = (const float*)d_in[10];
    const float* ct1_w  = (const float*)d_in[11];
    const float* ct1_b  = (const float*)d_in[12];
    const float* ct2_w  = (const float*)d_in[13];
    const float* ct2_b  = (const float*)d_in[14];
    const float* ct3_w  = (const float*)d_in[15];
    const float* ct3_b  = (const float*)d_in[16];
    const float* ct4_w  = (const float*)d_in[17];
    const float* ct4_b  = (const float*)d_in[18];
    const float* ct5_w  = (const float*)d_in[19];
    const float* ct5_b  = (const float*)d_in[20];
    float* out = (float*)d_out;

    cudaFuncSetAttribute(solver_kernel, cudaFuncAttributeMaxDynamicSharedMemorySize,
                         SMEM_FLOATS * (int)sizeof(float));
    cudaFuncSetAttribute(ctchain_kernel, cudaFuncAttributeMaxDynamicSharedMemorySize,
                         21248 * (int)sizeof(float));

    hyper_kernel<<<BATCH, 256>>>(kA, fc1_w1, fc1_b1, fc1_w2, fc1_b2,
                                 fc2_w1, fc2_b1, fc2_w2, fc2_b2);
    ctchain_kernel<<<BATCH, 512, 21248 * sizeof(float)>>>(kA, ct1_w, ct1_b, ct2_w, ct2_b,
                                                          ct3_w, ct3_b, ct4_w, ct4_b);
    init_tw_kernel<<<(63*68 + 255)/256, 256>>>();
    solver_kernel<<<BATCH, 512, SMEM_FLOATS * sizeof(float)>>>(x, f, kA, ct5_w, ct5_b);
    final_reduce_kernel<<<1, BATCH>>>(out);
}